// round 12
// baseline (speedup 1.0000x reference)
#include <cuda_runtime.h>
#include <math.h>
#include <stdint.h>

#define BTOT 8192      // B*T rows
#define CDIM 2048      // channels
#define TSEQ 2048      // sequence length
#define NHEAD 16
#define HDIM 128

// -------- scratch (device globals; allocation-free) --------
__device__ float g_nx [BTOT * CDIM];   // LN out: tf32-rounded, k-permuted
__device__ float g_q  [BTOT * CDIM];
__device__ float g_k  [BTOT * CDIM];
__device__ float g_v  [BTOT * CDIM];
__device__ float g_att[BTOT * CDIM];   // flash out: tf32-rounded, k-permuted
__device__ float g_wq [CDIM * CDIM];   // Wt[n][perm k], tf32
__device__ float g_wk [CDIM * CDIM];
__device__ float g_wv [CDIM * CDIM];
__device__ float g_wo [CDIM * CDIM];
__device__ float g_rope[TSEQ * 128];   // row t: [0..63]=cos(t*invf), [64..127]=sin

__device__ __forceinline__ float to_tf32(float x) {
    uint32_t u;
    asm("cvt.rna.tf32.f32 %0, %1;" : "=r"(u) : "f"(x));
    return __uint_as_float(u);
}
__device__ __forceinline__ float4 tf32x4(float4 v) {
    return make_float4(to_tf32(v.x), to_tf32(v.y), to_tf32(v.z), to_tf32(v.w));
}
// permute k within its 32-wide chunk: chunk | 8*(k&3) + ((k&31)>>2)
__device__ __forceinline__ int permk(int k) {
    return (k & ~31) | (((k & 3) << 3) | ((k & 31) >> 2));
}
__device__ __forceinline__ void cp_async16(uint32_t dst_smem, const void* src) {
    asm volatile("cp.async.cg.shared.global [%0], [%1], 16;\n"
                 :: "r"(dst_smem), "l"(src));
}
#define CP_COMMIT() asm volatile("cp.async.commit_group;\n" ::: "memory")
#define CP_WAIT(n)  asm volatile("cp.async.wait_group %0;\n" :: "n"(n) : "memory")

// ===================== Prep: LN + weight transform + rope table (one launch) ====
// blocks [0, 8192)          : LayerNorm rows (tf32-rounded, k-permuted)
// blocks [8192, 24576)      : Wt[n][perm k] = rna(W[k][n]), 4 weights
// blocks [24576, 25600)     : rope cos/sin table, 2 rows of t per block
__global__ __launch_bounds__(256) void prep_kernel(
    const float* __restrict__ x,
    const float* __restrict__ gamma, const float* __restrict__ beta,
    const float* __restrict__ Wq, const float* __restrict__ Wk,
    const float* __restrict__ Wv, const float* __restrict__ Wo) {
    __shared__ float sh[16];
    __shared__ float tile[32][33];
    int bx = blockIdx.x;
    int tid = threadIdx.x;

    if (bx < 8192) {                      // ---- LayerNorm ----
        int row = bx;
        const float* px = x + (size_t)row * CDIM;

        float4 a0 = *(const float4*)(px + tid * 4);
        float4 a1 = *(const float4*)(px + 1024 + tid * 4);

        float s = a0.x + a0.y + a0.z + a0.w + a1.x + a1.y + a1.z + a1.w;
        float q = a0.x*a0.x + a0.y*a0.y + a0.z*a0.z + a0.w*a0.w
                + a1.x*a1.x + a1.y*a1.y + a1.z*a1.z + a1.w*a1.w;

        #pragma unroll
        for (int off = 16; off; off >>= 1) {
            s += __shfl_xor_sync(0xffffffffu, s, off);
            q += __shfl_xor_sync(0xffffffffu, q, off);
        }
        if ((tid & 31) == 0) { sh[tid >> 5] = s; sh[8 + (tid >> 5)] = q; }
        __syncthreads();
        float ts = 0.f, tq = 0.f;
        #pragma unroll
        for (int i = 0; i < 8; i++) { ts += sh[i]; tq += sh[8 + i]; }

        float mu   = ts * (1.f / 2048.f);
        float var  = tq * (1.f / 2048.f) - mu * mu;
        float rstd = rsqrtf(var + 1e-5f);

        float4 g0 = *(const float4*)(gamma + tid * 4);
        float4 g1 = *(const float4*)(gamma + 1024 + tid * 4);
        float4 b0 = *(const float4*)(beta + tid * 4);
        float4 b1 = *(const float4*)(beta + 1024 + tid * 4);

        float* po = g_nx + (size_t)row * CDIM;
        float o[8];
        o[0] = (a0.x - mu) * rstd * g0.x + b0.x;
        o[1] = (a0.y - mu) * rstd * g0.y + b0.y;
        o[2] = (a0.z - mu) * rstd * g0.z + b0.z;
        o[3] = (a0.w - mu) * rstd * g0.w + b0.w;
        o[4] = (a1.x - mu) * rstd * g1.x + b1.x;
        o[5] = (a1.y - mu) * rstd * g1.y + b1.y;
        o[6] = (a1.z - mu) * rstd * g1.z + b1.z;
        o[7] = (a1.w - mu) * rstd * g1.w + b1.w;
        #pragma unroll
        for (int j = 0; j < 4; j++) {
            po[permk(4 * tid + j)]        = to_tf32(o[j]);
            po[permk(1024 + 4 * tid + j)] = to_tf32(o[4 + j]);
        }
    } else if (bx < 24576) {              // ---- weight transform ----
        int idx = bx - 8192;
        int z = idx >> 12;
        int rem = idx & 4095;
        int k0 = (rem >> 6) * 32, n0 = (rem & 63) * 32;
        const float* W = (z == 0) ? Wq : (z == 1) ? Wk : (z == 2) ? Wv : Wo;
        float* Wt = (z == 0) ? g_wq : (z == 1) ? g_wk : (z == 2) ? g_wv : g_wo;

        int c = tid & 31, r = tid >> 5;   // r 0..7
        #pragma unroll
        for (int i = 0; i < 4; i++)
            tile[r + 8 * i][c] = W[(size_t)(k0 + r + 8 * i) * CDIM + n0 + c];
        __syncthreads();
        int po = ((c & 3) << 3) | (c >> 2);
        #pragma unroll
        for (int i = 0; i < 4; i++)
            Wt[(size_t)(n0 + r + 8 * i) * CDIM + k0 + po] = to_tf32(tile[c][r + 8 * i]);
    } else {                              // ---- rope table ----
        int t = (bx - 24576) * 2 + (tid >> 7);
        int c = tid & 127;
        int f = c & 63;
        float inv = powf(10000.f, -(float)f / 64.f);
        float ang = (float)t * inv;
        g_rope[t * 128 + c] = (c < 64) ? cosf(ang) : sinf(ang);
    }
}

// ===================== tf32 GEMM v3.1 (R8) + fused RoPE epilogue =================
// Y = A*W + bias (+residual). A[M][2048] perm/tf32, Wt[n][perm k] tf32.
// 128x128 tile, BK=32, 256 thr, 8 warps (2x4), warp 64x32, 3-stage cp.async ring.
// MODE 0 (QKV): z<2 -> rope applied in epilogue via smem tile + table, tf32 out.
//               z==2 -> plain bias + tf32 round.
// MODE 1 (Wo):  bias + residual, fp32 out.
#define TG3_SMEM (6 * 4608 * 4)   // 110592 B

template<int MODE>
__global__ __launch_bounds__(256, 2) void tg3_kernel(
    const float* __restrict__ A,
    const float* __restrict__ B0, const float* __restrict__ B1, const float* __restrict__ B2,
    const float* __restrict__ c0, const float* __restrict__ c1, const float* __restrict__ c2,
    const float* __restrict__ R,
    float* __restrict__ Y0, float* __restrict__ Y1, float* __restrict__ Y2)
{
    const int N = CDIM;
    extern __shared__ float smp[];

    int z = blockIdx.z;
    const float* Wt   = (z == 0) ? B0 : (z == 1) ? B1 : B2;
    const float* bias = (z == 0) ? c0 : (z == 1) ? c1 : c2;
    float*       Y    = (z == 0) ? Y0 : (z == 1) ? Y1 : Y2;

    int tid = threadIdx.x, lane = tid & 31, warp = tid >> 5;
    int bm = blockIdx.y * 128, bn = blockIdx.x * 128;

    int srow = tid >> 3;
    int sq   = (tid & 7) * 4;

    const float* Ap = A  + (size_t)(bm + srow) * CDIM + sq;
    const float* Bp = Wt + (size_t)(bn + srow) * CDIM + sq;

    uint32_t sbase = (uint32_t)__cvta_generic_to_shared(smp);

    float c[4][4][4];
    #pragma unroll
    for (int mi = 0; mi < 4; mi++)
        #pragma unroll
        for (int ni = 0; ni < 4; ni++)
            #pragma unroll
            for (int r = 0; r < 4; r++) c[mi][ni][r] = 0.f;

    int wm = warp >> 2, wn = warp & 3;
    int mbase = wm * 64, nbase = wn * 32;
    int lq = lane >> 2, lr = lane & 3;

    auto issue = [&](int i, int s) {
        int k0 = i * 32;
        uint32_t da = sbase + (uint32_t)(s * 4608 + srow * 36 + sq) * 4;
        uint32_t db = sbase + (uint32_t)(13824 + s * 4608 + srow * 36 + sq) * 4;
        #pragma unroll
        for (int it = 0; it < 4; it++) {
            cp_async16(da + it * (32 * 36 * 4), Ap + (size_t)(it * 32) * CDIM + k0);
            cp_async16(db + it * (32 * 36 * 4), Bp + (size_t)(it * 32) * CDIM + k0);
        }
        CP_COMMIT();
    };

    issue(0, 0);
    issue(1, 1);

    const int NITER = CDIM / 32;   // 64
    for (int i = 0; i < NITER; ++i) {
        int s = i - (i / 3) * 3;
        if (i == NITER - 1) { CP_WAIT(0); } else { CP_WAIT(1); }
        __syncthreads();
        if (i + 2 < NITER) issue(i + 2, (i + 2) % 3);

        const float* Ab = smp + s * 4608;
        const float* Bb = smp + 13824 + s * 4608;

        #pragma unroll
        for (int pp = 0; pp < 2; pp++) {
            float4 fb[4];
            #pragma unroll
            for (int ni = 0; ni < 4; ni++)
                fb[ni] = *(const float4*)(Bb + (nbase + ni * 8 + lq) * 36 + 8 * lr + 4 * pp);
            #pragma unroll
            for (int mi = 0; mi < 4; mi++) {
                int r0 = mbase + mi * 16 + lq;
                float4 qa0 = *(const float4*)(Ab + r0 * 36 + 8 * lr + 4 * pp);
                float4 qa1 = *(const float4*)(Ab + (r0 + 8) * 36 + 8 * lr + 4 * pp);
                #pragma unroll
                for (int ni = 0; ni < 4; ni++)
                    asm volatile(
                        "mma.sync.aligned.m16n8k8.row.col.f32.tf32.tf32.f32 "
                        "{%0,%1,%2,%3}, {%4,%5,%6,%7}, {%8,%9}, {%0,%1,%2,%3};"
                        : "+f"(c[mi][ni][0]), "+f"(c[mi][ni][1]),
                          "+f"(c[mi][ni][2]), "+f"(c[mi][ni][3])
                        : "r"(__float_as_uint(qa0.x)), "r"(__float_as_uint(qa1.x)),
                          "r"(__float_as_uint(qa0.y)), "r"(__float_as_uint(qa1.y)),
                          "r"(__float_as_uint(fb[ni].x)), "r"(__float_as_uint(fb[ni].y)));
                #pragma unroll
                for (int ni = 0; ni < 4; ni++)
                    asm volatile(
                        "mma.sync.aligned.m16n8k8.row.col.f32.tf32.tf32.f32 "
                        "{%0,%1,%2,%3}, {%4,%5,%6,%7}, {%8,%9}, {%0,%1,%2,%3};"
                        : "+f"(c[mi][ni][0]), "+f"(c[mi][ni][1]),
                          "+f"(c[mi][ni][2]), "+f"(c[mi][ni][3])
                        : "r"(__float_as_uint(qa0.z)), "r"(__float_as_uint(qa1.z)),
                          "r"(__float_as_uint(qa0.w)), "r"(__float_as_uint(qa1.w)),
                          "r"(__float_as_uint(fb[ni].z)), "r"(__float_as_uint(fb[ni].w)));
            }
        }
    }

    if (MODE == 0 && z < 2) {
        // ---- fused RoPE epilogue: stage tile in (now free) smem ring ----
        __syncthreads();                       // mainloop smem reads done
        float* tr = smp;                       // [128][132]
        #pragma unroll
        for (int mi = 0; mi < 4; mi++) {
            int r0 = mbase + mi * 16 + lq;
            #pragma unroll
            for (int ni = 0; ni < 4; ni++) {
                int cb = nbase + ni * 8 + 2 * lr;
                float bx = bias[bn + cb], by = bias[bn + cb + 1];
                *(float2*)&tr[r0 * 132 + cb] =
                    make_float2(c[mi][ni][0] + bx, c[mi][ni][1] + by);
                *(float2*)&tr[(r0 + 8) * 132 + cb] =
                    make_float2(c[mi][ni][2] + bx, c[mi][ni][3] + by);
            }
        }
        __syncthreads();

        // rotation: bn block == one head (128-wide); pairs (f, f+64) are local
        int row = tid >> 1, f0 = (tid & 1) * 32;
        int t = (bm + row) & (TSEQ - 1);
        const float* tab = g_rope + t * 128;
        float* Yr = Y + (size_t)(bm + row) * CDIM + bn;
        #pragma unroll
        for (int j = 0; j < 8; j++) {
            float4 a  = *(float4*)&tr[row * 132 + f0 + j * 4];
            float4 b2 = *(float4*)&tr[row * 132 + 64 + f0 + j * 4];
            float4 cs = *(const float4*)(tab + f0 + j * 4);
            float4 sn = *(const float4*)(tab + 64 + f0 + j * 4);
            float4 o1 = make_float4(a.x * cs.x - b2.x * sn.x,
                                    a.y * cs.y - b2.y * sn.y,
                                    a.z * cs.z - b2.z * sn.z,
                                    a.w * cs.w - b2.w * sn.w);
            float4 o2 = make_float4(b2.x * cs.x + a.x * sn.x,
                                    b2.y * cs.y + a.y * sn.y,
                                    b2.z * cs.z + a.z * sn.z,
                                    b2.w * cs.w + a.w * sn.w);
            *(float4*)(Yr + f0 + j * 4)      = tf32x4(o1);
            *(float4*)(Yr + 64 + f0 + j * 4) = tf32x4(o2);
        }
    } else {
        // ---- plain epilogue (v and Wo paths) ----
        #pragma unroll
        for (int mi = 0; mi < 4; mi++) {
            int r0 = bm + mbase + mi * 16 + lq;
            #pragma unroll
            for (int ni = 0; ni < 4; ni++) {
                int cb = bn + nbase + ni * 8 + 2 * lr;
                float bx = bias[cb], by = bias[cb + 1];
                float2 v0 = make_float2(c[mi][ni][0] + bx, c[mi][ni][1] + by);
                float2 v1 = make_float2(c[mi][ni][2] + bx, c[mi][ni][3] + by);
                if (MODE == 1) {
                    float2 r0v = *(const float2*)(R + (size_t)r0 * N + cb);
                    float2 r1v = *(const float2*)(R + (size_t)(r0 + 8) * N + cb);
                    v0.x += r0v.x; v0.y += r0v.y;
                    v1.x += r1v.x; v1.y += r1v.y;
                } else {
                    v0.x = to_tf32(v0.x); v0.y = to_tf32(v0.y);
                    v1.x = to_tf32(v1.x); v1.y = to_tf32(v1.y);
                }
                *(float2*)(Y + (size_t)r0 * N + cb)       = v0;
                *(float2*)(Y + (size_t)(r0 + 8) * N + cb) = v1;
            }
        }
    }
}

// ===================== Flash attention v3 (unchanged from R8) =====================
#define FLASH3_SMEM (51200 * 4)   // Qs 16896 + K0/K1 8448*2 + Vs 8704 + Ps 8704

__global__ __launch_bounds__(256, 1) void flash_tc_kernel() {
    extern __shared__ float sm[];
    float* Qs = sm;                    // [128][132]
    float* K0 = sm + 16896;            // [64][132]
    float* K1 = sm + 25344;            // [64][132]
    float* Vs = sm + 33792;            // [64][136]
    float* Ps = sm + 42496;            // [128][68]
    uint32_t sb  = (uint32_t)__cvta_generic_to_shared(sm);
    uint32_t k0a = sb + 16896u * 4, k1a = sb + 25344u * 4, va = sb + 33792u * 4;

    int qb = gridDim.x - 1 - blockIdx.x;
    int h = blockIdx.y, b = blockIdx.z;
    int tid = threadIdx.x, lane = tid & 31, warp = tid >> 5;
    int lq = lane >> 2, lr = lane & 3;

    size_t base = ((size_t)b * TSEQ) * CDIM + (size_t)h * HDIM;

    #pragma unroll
    for (int it = 0; it < 16; it++) {
        int f4 = tid + it * 256;
        int r  = f4 >> 5;
        int c4 = (f4 & 31) * 4;
        float4 v = *(const float4*)(g_q + base + (size_t)(qb * 128 + r) * CDIM + c4);
        *(float4*)&Qs[r * 132 + c4] = tf32x4(v);
    }

    float m0 = -1e30f, m1 = -1e30f, l0 = 0.f, l1 = 0.f;
    float O[16][4];
    #pragma unroll
    for (int nt = 0; nt < 16; nt++)
        #pragma unroll
        for (int r = 0; r < 4; r++) O[nt][r] = 0.f;

    const float scale = 0.08838834764831845f;
    int arow = warp * 16 + lq;
    int prow0 = arow * 68, prow1 = (arow + 8) * 68;
    int grow0 = qb * 128 + arow;
    int nkb = 2 * (qb + 1);

    #pragma unroll
    for (int it = 0; it < 8; it++) {
        int f4 = tid + it * 256;
        int r  = f4 >> 5;
        int c4 = (f4 & 31) * 4;
        cp_async16(k0a + (uint32_t)(r * 132 + c4) * 4,
                   g_k + base + (size_t)r * CDIM + c4);
    }
    CP_COMMIT();

    for (int kb = 0; kb < nkb; kb++) {
        __syncthreads();

        #pragma unroll
        for (int it = 0; it < 8; it++) {
            int f4 = tid + it * 256;
            int r  = f4 >> 5;
            int c4 = (f4 & 31) * 4;
            cp_async16(va + (uint32_t)(r * 136 + c4) * 4,
                       g_v + base + (size_t)(kb * 64 + r) * CDIM + c4);
        }
        CP_COMMIT();

        bool more = (kb + 1 < nkb);
        if (more) {
            uint32_t ka = ((kb + 1) & 1) ? k1a : k0a;
            #pragma unroll
            for (int it = 0; it < 8; it++) {
                int f4 = tid + it * 256;
                int r  = f4 >> 5;
                int c4 = (f4 & 31) * 4;
                cp_async16(ka + (uint32_t)(r * 132 + c4) * 4,
                           g_k + base + (size_t)((kb + 1) * 64 + r) * CDIM + c4);
            }
            CP_COMMIT();
        }

        if (more) { CP_WAIT(2); } else { CP_WAIT(1); }
        __syncthreads();

        const float* Kc = (kb & 1) ? K1 : K0;

        float s[8][4];
        #pragma unroll
        for (int nt = 0; nt < 8; nt++)
            #pragma unroll
            for (int r = 0; r < 4; r++) s[nt][r] = 0.f;

        #pragma unroll
        for (int kt = 0; kt < 16; kt++) {
            int kk = kt * 8;
            uint32_t a0 = __float_as_uint(Qs[arow * 132 + kk + lr]);
            uint32_t a1 = __float_as_uint(Qs[(arow + 8) * 132 + kk + lr]);
            uint32_t a2 = __float_as_uint(Qs[arow * 132 + kk + lr + 4]);
            uint32_t a3 = __float_as_uint(Qs[(arow + 8) * 132 + kk + lr + 4]);
            #pragma unroll
            for (int nt = 0; nt < 8; nt++) {
                int nc = nt * 8 + lq;
                uint32_t b0 = __float_as_uint(Kc[nc * 132 + kk + lr]);
                uint32_t b1 = __float_as_uint(Kc[nc * 132 + kk + lr + 4]);
                asm volatile(
                    "mma.sync.aligned.m16n8k8.row.col.f32.tf32.tf32.f32 "
                    "{%0,%1,%2,%3}, {%4,%5,%6,%7}, {%8,%9}, {%0,%1,%2,%3};"
                    : "+f"(s[nt][0]), "+f"(s[nt][1]), "+f"(s[nt][2]), "+f"(s[nt][3])
                    : "r"(a0), "r"(a1), "r"(a2), "r"(a3), "r"(b0), "r"(b1));
            }
        }

        bool needmask = (kb * 64 + 63 > qb * 128 + warp * 16);
        float t0 = -1e30f, t1 = -1e30f;
        #pragma unroll
        for (int nt = 0; nt < 8; nt++) {
            if (needmask) {
                int cc0 = kb * 64 + nt * 8 + 2 * lr;
                s[nt][0] = (cc0     <= grow0)     ? s[nt][0] * scale : -1e30f;
                s[nt][1] = (cc0 + 1 <= grow0)     ? s[nt][1] * scale : -1e30f;
                s[nt][2] = (cc0     <= grow0 + 8) ? s[nt][2] * scale : -1e30f;
                s[nt][3] = (cc0 + 1 <= grow0 + 8) ? s[nt][3] * scale : -1e30f;
            } else {
                s[nt][0] *= scale; s[nt][1] *= scale;
                s[nt][2] *= scale; s[nt][3] *= scale;
            }
            t0 = fmaxf(t0, fmaxf(s[nt][0], s[nt][1]));
            t1 = fmaxf(t1, fmaxf(s[nt][2], s[nt][3]));
        }
        t0 = fmaxf(t0, __shfl_xor_sync(0xffffffffu, t0, 1));
        t0 = fmaxf(t0, __shfl_xor_sync(0xffffffffu, t0, 2));
        t1 = fmaxf(t1, __shfl_xor_sync(0xffffffffu, t1, 1));
        t1 = fmaxf(t1, __shfl_xor_sync(0xffffffffu, t1, 2));

        float mn0 = fmaxf(m0, t0), mn1 = fmaxf(m1, t1);
        float al0 = __expf(m0 - mn0), al1 = __expf(m1 - mn1);
        float rs0 = 0.f, rs1 = 0.f;
        #pragma unroll
        for (int nt = 0; nt < 8; nt++) {
            float p00 = to_tf32(__expf(s[nt][0] - mn0));
            float p01 = to_tf32(__expf(s[nt][1] - mn0));
            float p10 = to_tf32(__expf(s[nt][2] - mn1));
            float p11 = to_tf32(__expf(s[nt][3] - mn1));
            rs0 += p00 + p01;
            rs1 += p10 + p11;
            *(float2*)&Ps[prow0 + nt * 8 + 2 * lr] = make_float2(p00, p01);
            *(float2*)&Ps[prow1 + nt * 8 + 2 * lr] = make_float2(p10, p11);
        }
        rs0 += __shfl_xor_sync(0xffffffffu, rs0, 1);
        rs0 += __shfl_xor_sync(0xffffffffu, rs0, 2);
        rs1 += __shfl_xor_sync(0xffffffffu, rs1, 1);
        rs1 += __shfl_xor_sync(0xffffffffu, rs1, 2);

        l0 = l0 * al0 + rs0;  l1 = l1 * al1 + rs1;
        m0 = mn0;             m1 = mn1;
        #pragma unroll
        for (int nt = 0; nt < 16; nt++) {
            O[nt][0] *= al0; O[nt][1] *= al0;
            O[nt][2] *= al1; O[nt][3] *= al1;
        }
        __syncwarp();

        if (more) { CP_WAIT(1); } else { CP_WAIT(0); }
        __syncthreads();

        #pragma unroll
        for (int kt = 0; kt < 8; kt++) {
            int kk = kt * 8;
            uint32_t a0 = __float_as_uint(Ps[prow0 + kk + lr]);
            uint32_t a1 = __float_as_uint(Ps[prow1 + kk + lr]);
            uint32_t a2 = __float_as_uint(Ps[prow0 + kk + lr + 4]);
            uint32_t a3 = __float_as_uint(Ps[prow1 + kk + lr + 4]);
            #pragma unroll
            for (int nt = 0; nt < 16; nt++) {
                int nc = nt * 8 + lq;
                uint32_t b0 = __float_as_uint(Vs[(kk + lr) * 136 + nc]);
                uint32_t b1 = __float_as_uint(Vs[(kk + lr + 4) * 136 + nc]);
                asm volatile(
                    "mma.sync.aligned.m16n8k8.row.col.f32.tf32.tf32.f32 "
                    "{%0,%1,%2,%3}, {%4,%5,%6,%7}, {%8,%9}, {%0,%1,%2,%3};"
                    : "+f"(O[nt][0]), "+f"(O[nt][1]), "+f"(O[nt][2]), "+f"(O[nt][3])
                    : "r"(a0), "r"(a1), "r"(a2), "r"(a3), "r"(b0), "r"(b1));
            }
        }
    }

    // epilogue: normalize, tf32-round, write k-PERMUTED (GEMM-A layout)
    float inv0 = 1.f / l0, inv1 = 1.f / l1;
    size_t row0 = (size_t)b * TSEQ + grow0;
    #pragma unroll
    for (int nt = 0; nt < 16; nt++) {
        int col = h * HDIM + nt * 8 + 2 * lr;
        int p0 = permk(col), p1 = permk(col + 1);
        g_att[row0 * CDIM + p0]       = to_tf32(O[nt][0] * inv0);
        g_att[row0 * CDIM + p1]       = to_tf32(O[nt][1] * inv0);
        g_att[(row0 + 8) * CDIM + p0] = to_tf32(O[nt][2] * inv1);
        g_att[(row0 + 8) * CDIM + p1] = to_tf32(O[nt][3] * inv1);
    }
}

// ===================== launch =====================
extern "C" void kernel_launch(void* const* d_in, const int* in_sizes, int n_in,
                              void* d_out, int out_size) {
    const float* x    = (const float*)d_in[0];
    const float* ln_g = (const float*)d_in[1];
    const float* ln_b = (const float*)d_in[2];
    const float* Wq   = (const float*)d_in[3];
    const float* bq   = (const float*)d_in[4];
    const float* Wk   = (const float*)d_in[5];
    const float* bk   = (const float*)d_in[6];
    const float* Wv   = (const float*)d_in[7];
    const float* bv   = (const float*)d_in[8];
    const float* Wo   = (const float*)d_in[9];
    const float* bo   = (const float*)d_in[10];
    float* out = (float*)d_out;

    float *nx, *qp, *kp, *vp, *ap, *wq, *wk, *wv, *wo;
    cudaGetSymbolAddress((void**)&nx, g_nx);
    cudaGetSymbolAddress((void**)&qp, g_q);
    cudaGetSymbolAddress((void**)&kp, g_k);
    cudaGetSymbolAddress((void**)&vp, g_v);
    cudaGetSymbolAddress((void**)&ap, g_att);
    cudaGetSymbolAddress((void**)&wq, g_wq);
    cudaGetSymbolAddress((void**)&wk, g_wk);
    cudaGetSymbolAddress((void**)&wv, g_wv);
    cudaGetSymbolAddress((void**)&wo, g_wo);

    cudaFuncSetAttribute(flash_tc_kernel, cudaFuncAttributeMaxDynamicSharedMemorySize, FLASH3_SMEM);
    cudaFuncSetAttribute(tg3_kernel<0>, cudaFuncAttributeMaxDynamicSharedMemorySize, TG3_SMEM);
    cudaFuncSetAttribute(tg3_kernel<1>, cudaFuncAttributeMaxDynamicSharedMemorySize, TG3_SMEM);

    // LN + weight transform + rope table, one launch
    prep_kernel<<<25600, 256>>>(x, ln_g, ln_b, Wq, Wk, Wv, Wo);

    // fused Q/K/V projections (rope applied in epilogue for q,k)
    tg3_kernel<0><<<dim3(16, 64, 3), 256, TG3_SMEM>>>(
        nx, wq, wk, wv, bq, bk, bv, nullptr, qp, kp, vp);

    flash_tc_kernel<<<dim3(TSEQ / 128, NHEAD, 4), 256, FLASH3_SMEM>>>();

    // output projection + residual
    tg3_kernel<1><<<dim3(16, 64, 1), 256, TG3_SMEM>>>(
        ap, wo, wo, wo, bo, bo, bo, x, out, out, out);
}

// round 13
// speedup vs baseline: 1.8048x; 1.8048x over previous
#include <cuda_runtime.h>
#include <cuda_bf16.h>
#include <math.h>
#include <stdint.h>

#define BTOT 8192      // B*T rows
#define CDIM 2048      // channels
#define TSEQ 2048      // sequence length
#define NHEAD 16
#define HDIM 128

// -------- scratch (device globals; allocation-free) --------
__device__ __nv_bfloat16 g_nx [BTOT * CDIM];   // LN out, bf16, natural layout
__device__ float         g_q  [BTOT * CDIM];   // fp32 (flash consumes tf32-rounded)
__device__ float         g_k  [BTOT * CDIM];
__device__ float         g_v  [BTOT * CDIM];
__device__ __nv_bfloat16 g_att[BTOT * CDIM];   // flash out, bf16, natural layout
__device__ __nv_bfloat16 g_wq [CDIM * CDIM];   // Wt[n][k] transposed, bf16
__device__ __nv_bfloat16 g_wk [CDIM * CDIM];
__device__ __nv_bfloat16 g_wv [CDIM * CDIM];
__device__ __nv_bfloat16 g_wo [CDIM * CDIM];

__device__ __forceinline__ float to_tf32(float x) {
    uint32_t u;
    asm("cvt.rna.tf32.f32 %0, %1;" : "=r"(u) : "f"(x));
    return __uint_as_float(u);
}
__device__ __forceinline__ float4 tf32x4(float4 v) {
    return make_float4(to_tf32(v.x), to_tf32(v.y), to_tf32(v.z), to_tf32(v.w));
}
__device__ __forceinline__ void cp_async16(uint32_t dst_smem, const void* src) {
    asm volatile("cp.async.cg.shared.global [%0], [%1], 16;\n"
                 :: "r"(dst_smem), "l"(src));
}
#define CP_COMMIT() asm volatile("cp.async.commit_group;\n" ::: "memory")
#define CP_WAIT(n)  asm volatile("cp.async.wait_group %0;\n" :: "n"(n) : "memory")

#define LDMX4(r0, r1, r2, r3, addr) \
    asm volatile("ldmatrix.sync.aligned.m8n8.x4.shared.b16 {%0,%1,%2,%3}, [%4];" \
                 : "=r"(r0), "=r"(r1), "=r"(r2), "=r"(r3) : "r"(addr))
#define LDMX2(r0, r1, addr) \
    asm volatile("ldmatrix.sync.aligned.m8n8.x2.shared.b16 {%0,%1}, [%2];" \
                 : "=r"(r0), "=r"(r1) : "r"(addr))
#define MMA_BF16(c, a0, a1, a2, a3, b0, b1) \
    asm volatile("mma.sync.aligned.m16n8k16.row.col.f32.bf16.bf16.f32 " \
                 "{%0,%1,%2,%3}, {%4,%5,%6,%7}, {%8,%9}, {%0,%1,%2,%3};" \
                 : "+f"((c)[0]), "+f"((c)[1]), "+f"((c)[2]), "+f"((c)[3]) \
                 : "r"(a0), "r"(a1), "r"(a2), "r"(a3), "r"(b0), "r"(b1))

// ===================== LayerNorm (bf16 output, natural layout) =====================
__global__ __launch_bounds__(256) void ln_kernel(const float* __restrict__ x,
                                                 const float* __restrict__ gamma,
                                                 const float* __restrict__ beta) {
    int row = blockIdx.x;
    int tid = threadIdx.x;
    const float* px = x + (size_t)row * CDIM;

    float4 a0 = *(const float4*)(px + tid * 4);
    float4 a1 = *(const float4*)(px + 1024 + tid * 4);

    float s = a0.x + a0.y + a0.z + a0.w + a1.x + a1.y + a1.z + a1.w;
    float q = a0.x*a0.x + a0.y*a0.y + a0.z*a0.z + a0.w*a0.w
            + a1.x*a1.x + a1.y*a1.y + a1.z*a1.z + a1.w*a1.w;

    #pragma unroll
    for (int off = 16; off; off >>= 1) {
        s += __shfl_xor_sync(0xffffffffu, s, off);
        q += __shfl_xor_sync(0xffffffffu, q, off);
    }
    __shared__ float sh[16];
    if ((tid & 31) == 0) { sh[tid >> 5] = s; sh[8 + (tid >> 5)] = q; }
    __syncthreads();
    float ts = 0.f, tq = 0.f;
    #pragma unroll
    for (int i = 0; i < 8; i++) { ts += sh[i]; tq += sh[8 + i]; }

    float mu   = ts * (1.f / 2048.f);
    float var  = tq * (1.f / 2048.f) - mu * mu;
    float rstd = rsqrtf(var + 1e-5f);

    float4 g0 = *(const float4*)(gamma + tid * 4);
    float4 g1 = *(const float4*)(gamma + 1024 + tid * 4);
    float4 b0 = *(const float4*)(beta + tid * 4);
    float4 b1 = *(const float4*)(beta + 1024 + tid * 4);

    __nv_bfloat16* po = g_nx + (size_t)row * CDIM;
    float o[8];
    o[0] = (a0.x - mu) * rstd * g0.x + b0.x;
    o[1] = (a0.y - mu) * rstd * g0.y + b0.y;
    o[2] = (a0.z - mu) * rstd * g0.z + b0.z;
    o[3] = (a0.w - mu) * rstd * g0.w + b0.w;
    o[4] = (a1.x - mu) * rstd * g1.x + b1.x;
    o[5] = (a1.y - mu) * rstd * g1.y + b1.y;
    o[6] = (a1.z - mu) * rstd * g1.z + b1.z;
    o[7] = (a1.w - mu) * rstd * g1.w + b1.w;
    __nv_bfloat162 p0 = __floats2bfloat162_rn(o[0], o[1]);
    __nv_bfloat162 p1 = __floats2bfloat162_rn(o[2], o[3]);
    __nv_bfloat162 p2 = __floats2bfloat162_rn(o[4], o[5]);
    __nv_bfloat162 p3 = __floats2bfloat162_rn(o[6], o[7]);
    *(__nv_bfloat162*)(po + 4 * tid)          = p0;
    *(__nv_bfloat162*)(po + 4 * tid + 2)      = p1;
    *(__nv_bfloat162*)(po + 1024 + 4 * tid)   = p2;
    *(__nv_bfloat162*)(po + 1024 + 4 * tid + 2) = p3;
}

// ===================== Weight transform: Wt[n][k] = bf16(W[k][n]) =====================
__global__ __launch_bounds__(256) void wcvt_kernel(
    const float* __restrict__ Wq, const float* __restrict__ Wk,
    const float* __restrict__ Wv, const float* __restrict__ Wo) {
    __shared__ float tile[32][33];
    int z = blockIdx.z;
    const float* W = (z == 0) ? Wq : (z == 1) ? Wk : (z == 2) ? Wv : Wo;
    __nv_bfloat16* Wt = (z == 0) ? g_wq : (z == 1) ? g_wk : (z == 2) ? g_wv : g_wo;

    int k0 = blockIdx.x * 32, n0 = blockIdx.y * 32;
    int c = threadIdx.x & 31, r = threadIdx.x >> 5;   // r 0..7

    #pragma unroll
    for (int i = 0; i < 4; i++)
        tile[r + 8 * i][c] = W[(size_t)(k0 + r + 8 * i) * CDIM + n0 + c];
    __syncthreads();
    #pragma unroll
    for (int i = 0; i < 4; i++)
        Wt[(size_t)(n0 + r + 8 * i) * CDIM + k0 + c] = __float2bfloat16_rn(tile[c][r + 8 * i]);
}

// ===================== bf16 GEMM v5: m16n8k16, ldmatrix, SW128, 3-stage ring ======
// Y = A*W + bias (+residual). A[M][2048] bf16, Wt[n][2048] bf16 (both natural k).
// CTA 128x128, BK=64 (128B bf16 rows), 256 thr, 8 warps (2x4), warp 64x32.
// smem: A stage s at s*16KB; B stage s at 48KB + s*16KB.  98304 B total.
#define TG5_SMEM (6 * 16384)

template<int MODE>   // 0: +bias, tf32-rounded fp32 out ; 1: +bias+residual, fp32 out
__global__ __launch_bounds__(256, 2) void tg5_kernel(
    const __nv_bfloat16* __restrict__ A,
    const __nv_bfloat16* __restrict__ B0, const __nv_bfloat16* __restrict__ B1,
    const __nv_bfloat16* __restrict__ B2,
    const float* __restrict__ c0, const float* __restrict__ c1, const float* __restrict__ c2,
    const float* __restrict__ R,
    float* __restrict__ Y0, float* __restrict__ Y1, float* __restrict__ Y2)
{
    const int N = CDIM;
    extern __shared__ char sm5[];
    uint32_t sb = (uint32_t)__cvta_generic_to_shared(sm5);

    int z = blockIdx.z;
    const __nv_bfloat16* Wt = (z == 0) ? B0 : (z == 1) ? B1 : B2;
    const float* bias = (z == 0) ? c0 : (z == 1) ? c1 : c2;
    float*       Y    = (z == 0) ? Y0 : (z == 1) ? Y1 : Y2;

    int tid = threadIdx.x, lane = tid & 31, warp = tid >> 5;
    int bm = blockIdx.y * 128, bn = blockIdx.x * 128;

    // staging: thread -> row r (+32*it), 16B chunk cch; SW128 swizzle
    int r = tid >> 3, cch = tid & 7;
    uint32_t swoff = (uint32_t)(r * 128 + ((cch ^ (r & 7)) << 4));
    const __nv_bfloat16* Ap = A  + (size_t)(bm + r) * CDIM + cch * 8;
    const __nv_bfloat16* Bp = Wt + (size_t)(bn + r) * CDIM + cch * 8;

    float c[4][4][4];
    #pragma unroll
    for (int mi = 0; mi < 4; mi++)
        #pragma unroll
        for (int ni = 0; ni < 4; ni++)
            #pragma unroll
            for (int q = 0; q < 4; q++) c[mi][ni][q] = 0.f;

    int wm = warp >> 2, wn = warp & 3;
    int mbase = wm * 64, nbase = wn * 32;
    int lq = lane >> 2, lr = lane & 3;
    int l7 = lane & 7, lh = (lane >> 3) & 1, lg = lane >> 4;   // lg: 0/1

    auto issue = [&](int i, int s) {
        int k0 = i * 64;
        uint32_t da = sb + (uint32_t)s * 16384 + swoff;
        uint32_t db = sb + 49152u + (uint32_t)s * 16384 + swoff;
        #pragma unroll
        for (int it = 0; it < 4; it++) {
            cp_async16(da + it * 4096, Ap + (size_t)(it * 32) * CDIM + k0);
            cp_async16(db + it * 4096, Bp + (size_t)(it * 32) * CDIM + k0);
        }
        CP_COMMIT();
    };

    issue(0, 0);
    issue(1, 1);

    // fragment base addresses (row*128 bytes; chunk xor row&7)
    uint32_t arow = (uint32_t)(mbase + lh * 8 + l7);   // + mi*16
    uint32_t brow = (uint32_t)(nbase + l7);            // + ni*8

    const int NITER = CDIM / 64;   // 32
    for (int i = 0; i < NITER; ++i) {
        int s = i - (i / 3) * 3;   // i % 3
        if (i == NITER - 1) { CP_WAIT(0); } else { CP_WAIT(1); }
        __syncthreads();
        if (i + 2 < NITER) issue(i + 2, (i + 2) % 3);

        uint32_t Ab = sb + (uint32_t)s * 16384;
        uint32_t Bb = sb + 49152u + (uint32_t)s * 16384;

        #pragma unroll
        for (int kt = 0; kt < 4; kt++) {
            uint32_t b[4][2];
            uint32_t bch = (uint32_t)(((2 * kt + lh) ^ l7) << 4);
            #pragma unroll
            for (int ni = 0; ni < 4; ni++)
                LDMX2(b[ni][0], b[ni][1], Bb + (brow + ni * 8) * 128 + bch);
            uint32_t ach = (uint32_t)(((2 * kt + lg) ^ l7) << 4);
            #pragma unroll
            for (int mi = 0; mi < 4; mi++) {
                uint32_t a0, a1, a2, a3;
                LDMX4(a0, a1, a2, a3, Ab + (arow + mi * 16) * 128 + ach);
                #pragma unroll
                for (int ni = 0; ni < 4; ni++)
                    MMA_BF16(c[mi][ni], a0, a1, a2, a3, b[ni][0], b[ni][1]);
            }
        }
    }

    #pragma unroll
    for (int mi = 0; mi < 4; mi++) {
        int r0 = bm + mbase + mi * 16 + lq;
        #pragma unroll
        for (int ni = 0; ni < 4; ni++) {
            int cb = bn + nbase + ni * 8 + 2 * lr;
            float bx = bias[cb], by = bias[cb + 1];
            float2 v0 = make_float2(c[mi][ni][0] + bx, c[mi][ni][1] + by);
            float2 v1 = make_float2(c[mi][ni][2] + bx, c[mi][ni][3] + by);
            if (MODE == 1) {
                float2 r0v = *(const float2*)(R + (size_t)r0 * N + cb);
                float2 r1v = *(const float2*)(R + (size_t)(r0 + 8) * N + cb);
                v0.x += r0v.x; v0.y += r0v.y;
                v1.x += r1v.x; v1.y += r1v.y;
            } else {
                v0.x = to_tf32(v0.x); v0.y = to_tf32(v0.y);   // q/k/v feed flash
                v1.x = to_tf32(v1.x); v1.y = to_tf32(v1.y);
            }
            *(float2*)(Y + (size_t)r0 * N + cb)       = v0;
            *(float2*)(Y + (size_t)(r0 + 8) * N + cb) = v1;
        }
    }
}

// ===================== RoPE (in-place on fp32 q/k, writes tf32-rounded) ============
__global__ __launch_bounds__(256) void rope_kernel() {
    int row = blockIdx.x;
    float* buf = (blockIdx.y == 0) ? g_q : g_k;
    int t = row & (TSEQ - 1);

    __shared__ float cs[64], sn[64];
    if (threadIdx.x < 64) {
        float inv = powf(10000.f, -(float)threadIdx.x / 64.f);
        float ang = (float)t * inv;
        cs[threadIdx.x] = cosf(ang);
        sn[threadIdx.x] = sinf(ang);
    }
    __syncthreads();

    float* p = buf + (size_t)row * CDIM;
    for (int idx = threadIdx.x; idx < NHEAD * 64; idx += 256) {
        int h = idx >> 6, f = idx & 63;
        float a = p[h * 128 + f];
        float b = p[h * 128 + 64 + f];
        p[h * 128 + f]      = to_tf32(a * cs[f] - b * sn[f]);
        p[h * 128 + 64 + f] = to_tf32(b * cs[f] + a * sn[f]);
    }
}

// ===================== Flash attention v3 (R8; epilogue -> bf16 natural) ===========
#define FLASH3_SMEM (51200 * 4)   // Qs 16896 + K0/K1 8448*2 + Vs 8704 + Ps 8704

__global__ __launch_bounds__(256, 1) void flash_tc_kernel() {
    extern __shared__ float sm[];
    float* Qs = sm;                    // [128][132]
    float* K0 = sm + 16896;            // [64][132]
    float* K1 = sm + 25344;            // [64][132]
    float* Vs = sm + 33792;            // [64][136]
    float* Ps = sm + 42496;            // [128][68]
    uint32_t sb  = (uint32_t)__cvta_generic_to_shared(sm);
    uint32_t k0a = sb + 16896u * 4, k1a = sb + 25344u * 4, va = sb + 33792u * 4;

    int qb = gridDim.x - 1 - blockIdx.x;
    int h = blockIdx.y, b = blockIdx.z;
    int tid = threadIdx.x, lane = tid & 31, warp = tid >> 5;
    int lq = lane >> 2, lr = lane & 3;

    size_t base = ((size_t)b * TSEQ) * CDIM + (size_t)h * HDIM;

    #pragma unroll
    for (int it = 0; it < 16; it++) {
        int f4 = tid + it * 256;
        int r  = f4 >> 5;
        int c4 = (f4 & 31) * 4;
        float4 v = *(const float4*)(g_q + base + (size_t)(qb * 128 + r) * CDIM + c4);
        *(float4*)&Qs[r * 132 + c4] = tf32x4(v);
    }

    float m0 = -1e30f, m1 = -1e30f, l0 = 0.f, l1 = 0.f;
    float O[16][4];
    #pragma unroll
    for (int nt = 0; nt < 16; nt++)
        #pragma unroll
        for (int r = 0; r < 4; r++) O[nt][r] = 0.f;

    const float scale = 0.08838834764831845f;
    int arow = warp * 16 + lq;
    int prow0 = arow * 68, prow1 = (arow + 8) * 68;
    int grow0 = qb * 128 + arow;
    int nkb = 2 * (qb + 1);

    #pragma unroll
    for (int it = 0; it < 8; it++) {
        int f4 = tid + it * 256;
        int r  = f4 >> 5;
        int c4 = (f4 & 31) * 4;
        cp_async16(k0a + (uint32_t)(r * 132 + c4) * 4,
                   g_k + base + (size_t)r * CDIM + c4);
    }
    CP_COMMIT();

    for (int kb = 0; kb < nkb; kb++) {
        __syncthreads();

        #pragma unroll
        for (int it = 0; it < 8; it++) {
            int f4 = tid + it * 256;
            int r  = f4 >> 5;
            int c4 = (f4 & 31) * 4;
            cp_async16(va + (uint32_t)(r * 136 + c4) * 4,
                       g_v + base + (size_t)(kb * 64 + r) * CDIM + c4);
        }
        CP_COMMIT();

        bool more = (kb + 1 < nkb);
        if (more) {
            uint32_t ka = ((kb + 1) & 1) ? k1a : k0a;
            #pragma unroll
            for (int it = 0; it < 8; it++) {
                int f4 = tid + it * 256;
                int r  = f4 >> 5;
                int c4 = (f4 & 31) * 4;
                cp_async16(ka + (uint32_t)(r * 132 + c4) * 4,
                           g_k + base + (size_t)((kb + 1) * 64 + r) * CDIM + c4);
            }
            CP_COMMIT();
        }

        if (more) { CP_WAIT(2); } else { CP_WAIT(1); }
        __syncthreads();

        const float* Kc = (kb & 1) ? K1 : K0;

        float s[8][4];
        #pragma unroll
        for (int nt = 0; nt < 8; nt++)
            #pragma unroll
            for (int r = 0; r < 4; r++) s[nt][r] = 0.f;

        #pragma unroll
        for (int kt = 0; kt < 16; kt++) {
            int kk = kt * 8;
            uint32_t a0 = __float_as_uint(Qs[arow * 132 + kk + lr]);
            uint32_t a1 = __float_as_uint(Qs[(arow + 8) * 132 + kk + lr]);
            uint32_t a2 = __float_as_uint(Qs[arow * 132 + kk + lr + 4]);
            uint32_t a3 = __float_as_uint(Qs[(arow + 8) * 132 + kk + lr + 4]);
            #pragma unroll
            for (int nt = 0; nt < 8; nt++) {
                int nc = nt * 8 + lq;
                uint32_t b0 = __float_as_uint(Kc[nc * 132 + kk + lr]);
                uint32_t b1 = __float_as_uint(Kc[nc * 132 + kk + lr + 4]);
                asm volatile(
                    "mma.sync.aligned.m16n8k8.row.col.f32.tf32.tf32.f32 "
                    "{%0,%1,%2,%3}, {%4,%5,%6,%7}, {%8,%9}, {%0,%1,%2,%3};"
                    : "+f"(s[nt][0]), "+f"(s[nt][1]), "+f"(s[nt][2]), "+f"(s[nt][3])
                    : "r"(a0), "r"(a1), "r"(a2), "r"(a3), "r"(b0), "r"(b1));
            }
        }

        bool needmask = (kb * 64 + 63 > qb * 128 + warp * 16);
        float t0 = -1e30f, t1 = -1e30f;
        #pragma unroll
        for (int nt = 0; nt < 8; nt++) {
            if (needmask) {
                int cc0 = kb * 64 + nt * 8 + 2 * lr;
                s[nt][0] = (cc0     <= grow0)     ? s[nt][0] * scale : -1e30f;
                s[nt][1] = (cc0 + 1 <= grow0)     ? s[nt][1] * scale : -1e30f;
                s[nt][2] = (cc0     <= grow0 + 8) ? s[nt][2] * scale : -1e30f;
                s[nt][3] = (cc0 + 1 <= grow0 + 8) ? s[nt][3] * scale : -1e30f;
            } else {
                s[nt][0] *= scale; s[nt][1] *= scale;
                s[nt][2] *= scale; s[nt][3] *= scale;
            }
            t0 = fmaxf(t0, fmaxf(s[nt][0], s[nt][1]));
            t1 = fmaxf(t1, fmaxf(s[nt][2], s[nt][3]));
        }
        t0 = fmaxf(t0, __shfl_xor_sync(0xffffffffu, t0, 1));
        t0 = fmaxf(t0, __shfl_xor_sync(0xffffffffu, t0, 2));
        t1 = fmaxf(t1, __shfl_xor_sync(0xffffffffu, t1, 1));
        t1 = fmaxf(t1, __shfl_xor_sync(0xffffffffu, t1, 2));

        float mn0 = fmaxf(m0, t0), mn1 = fmaxf(m1, t1);
        float al0 = __expf(m0 - mn0), al1 = __expf(m1 - mn1);
        float rs0 = 0.f, rs1 = 0.f;
        #pragma unroll
        for (int nt = 0; nt < 8; nt++) {
            float p00 = to_tf32(__expf(s[nt][0] - mn0));
            float p01 = to_tf32(__expf(s[nt][1] - mn0));
            float p10 = to_tf32(__expf(s[nt][2] - mn1));
            float p11 = to_tf32(__expf(s[nt][3] - mn1));
            rs0 += p00 + p01;
            rs1 += p10 + p11;
            *(float2*)&Ps[prow0 + nt * 8 + 2 * lr] = make_float2(p00, p01);
            *(float2*)&Ps[prow1 + nt * 8 + 2 * lr] = make_float2(p10, p11);
        }
        rs0 += __shfl_xor_sync(0xffffffffu, rs0, 1);
        rs0 += __shfl_xor_sync(0xffffffffu, rs0, 2);
        rs1 += __shfl_xor_sync(0xffffffffu, rs1, 1);
        rs1 += __shfl_xor_sync(0xffffffffu, rs1, 2);

        l0 = l0 * al0 + rs0;  l1 = l1 * al1 + rs1;
        m0 = mn0;             m1 = mn1;
        #pragma unroll
        for (int nt = 0; nt < 16; nt++) {
            O[nt][0] *= al0; O[nt][1] *= al0;
            O[nt][2] *= al1; O[nt][3] *= al1;
        }
        __syncwarp();

        if (more) { CP_WAIT(1); } else { CP_WAIT(0); }
        __syncthreads();

        #pragma unroll
        for (int kt = 0; kt < 8; kt++) {
            int kk = kt * 8;
            uint32_t a0 = __float_as_uint(Ps[prow0 + kk + lr]);
            uint32_t a1 = __float_as_uint(Ps[prow1 + kk + lr]);
            uint32_t a2 = __float_as_uint(Ps[prow0 + kk + lr + 4]);
            uint32_t a3 = __float_as_uint(Ps[prow1 + kk + lr + 4]);
            #pragma unroll
            for (int nt = 0; nt < 16; nt++) {
                int nc = nt * 8 + lq;
                uint32_t b0 = __float_as_uint(Vs[(kk + lr) * 136 + nc]);
                uint32_t b1 = __float_as_uint(Vs[(kk + lr + 4) * 136 + nc]);
                asm volatile(
                    "mma.sync.aligned.m16n8k8.row.col.f32.tf32.tf32.f32 "
                    "{%0,%1,%2,%3}, {%4,%5,%6,%7}, {%8,%9}, {%0,%1,%2,%3};"
                    : "+f"(O[nt][0]), "+f"(O[nt][1]), "+f"(O[nt][2]), "+f"(O[nt][3])
                    : "r"(a0), "r"(a1), "r"(a2), "r"(a3), "r"(b0), "r"(b1));
            }
        }
    }

    // epilogue: normalize, write bf16 natural layout (feeds bf16 Wo GEMM)
    float inv0 = 1.f / l0, inv1 = 1.f / l1;
    size_t row0 = (size_t)b * TSEQ + grow0;
    #pragma unroll
    for (int nt = 0; nt < 16; nt++) {
        int col = h * HDIM + nt * 8 + 2 * lr;
        *(__nv_bfloat162*)(g_att + row0 * CDIM + col) =
            __floats2bfloat162_rn(O[nt][0] * inv0, O[nt][1] * inv0);
        *(__nv_bfloat162*)(g_att + (row0 + 8) * CDIM + col) =
            __floats2bfloat162_rn(O[nt][2] * inv1, O[nt][3] * inv1);
    }
}

// ===================== launch =====================
extern "C" void kernel_launch(void* const* d_in, const int* in_sizes, int n_in,
                              void* d_out, int out_size) {
    const float* x    = (const float*)d_in[0];
    const float* ln_g = (const float*)d_in[1];
    const float* ln_b = (const float*)d_in[2];
    const float* Wq   = (const float*)d_in[3];
    const float* bq   = (const float*)d_in[4];
    const float* Wk   = (const float*)d_in[5];
    const float* bk   = (const float*)d_in[6];
    const float* Wv   = (const float*)d_in[7];
    const float* bv   = (const float*)d_in[8];
    const float* Wo   = (const float*)d_in[9];
    const float* bo   = (const float*)d_in[10];
    float* out = (float*)d_out;

    __nv_bfloat16 *nx, *ap, *wq, *wk, *wv, *wo;
    float *qp, *kp, *vp;
    cudaGetSymbolAddress((void**)&nx, g_nx);
    cudaGetSymbolAddress((void**)&qp, g_q);
    cudaGetSymbolAddress((void**)&kp, g_k);
    cudaGetSymbolAddress((void**)&vp, g_v);
    cudaGetSymbolAddress((void**)&ap, g_att);
    cudaGetSymbolAddress((void**)&wq, g_wq);
    cudaGetSymbolAddress((void**)&wk, g_wk);
    cudaGetSymbolAddress((void**)&wv, g_wv);
    cudaGetSymbolAddress((void**)&wo, g_wo);

    cudaFuncSetAttribute(flash_tc_kernel, cudaFuncAttributeMaxDynamicSharedMemorySize, FLASH3_SMEM);
    cudaFuncSetAttribute(tg5_kernel<0>, cudaFuncAttributeMaxDynamicSharedMemorySize, TG5_SMEM);
    cudaFuncSetAttribute(tg5_kernel<1>, cudaFuncAttributeMaxDynamicSharedMemorySize, TG5_SMEM);

    ln_kernel<<<BTOT, 256>>>(x, ln_g, ln_b);
    wcvt_kernel<<<dim3(64, 64, 4), 256>>>(Wq, Wk, Wv, Wo);

    // fused Q/K/V projections (bf16 tensor cores)
    tg5_kernel<0><<<dim3(16, 64, 3), 256, TG5_SMEM>>>(
        nx, wq, wk, wv, bq, bk, bv, nullptr, qp, kp, vp);

    rope_kernel<<<dim3(BTOT, 2), 256>>>();

    flash_tc_kernel<<<dim3(TSEQ / 128, NHEAD, 4), 256, FLASH3_SMEM>>>();

    // output projection + residual (bf16 tensor cores)
    tg5_kernel<1><<<dim3(16, 64, 1), 256, TG5_SMEM>>>(
        ap, wo, wo, wo, bo, bo, bo, x, out, out, out);
}

// round 14
// speedup vs baseline: 2.2874x; 1.2674x over previous
#include <cuda_runtime.h>
#include <cuda_bf16.h>
#include <math.h>
#include <stdint.h>

#define BTOT 8192      // B*T rows
#define CDIM 2048      // channels
#define TSEQ 2048      // sequence length
#define NHEAD 16
#define HDIM 128

// -------- scratch (device globals; allocation-free) --------
__device__ __nv_bfloat16 g_nx [BTOT * CDIM];   // LN out, bf16
__device__ float         g_q  [BTOT * CDIM];   // proj out fp32 (pre-rope)
__device__ float         g_k  [BTOT * CDIM];
__device__ __nv_bfloat16 g_qb [BTOT * CDIM];   // rope out, bf16
__device__ __nv_bfloat16 g_kb [BTOT * CDIM];
__device__ __nv_bfloat16 g_vb [BTOT * CDIM];   // v, bf16 (straight from GEMM)
__device__ __nv_bfloat16 g_att[BTOT * CDIM];   // flash out, bf16
__device__ __nv_bfloat16 g_wq [CDIM * CDIM];   // Wt[n][k], bf16
__device__ __nv_bfloat16 g_wk [CDIM * CDIM];
__device__ __nv_bfloat16 g_wv [CDIM * CDIM];
__device__ __nv_bfloat16 g_wo [CDIM * CDIM];

__device__ __forceinline__ void cp_async16(uint32_t dst_smem, const void* src) {
    asm volatile("cp.async.cg.shared.global [%0], [%1], 16;\n"
                 :: "r"(dst_smem), "l"(src));
}
#define CP_COMMIT() asm volatile("cp.async.commit_group;\n" ::: "memory")
#define CP_WAIT(n)  asm volatile("cp.async.wait_group %0;\n" :: "n"(n) : "memory")

#define LDMX4(r0, r1, r2, r3, addr) \
    asm volatile("ldmatrix.sync.aligned.m8n8.x4.shared.b16 {%0,%1,%2,%3}, [%4];" \
                 : "=r"(r0), "=r"(r1), "=r"(r2), "=r"(r3) : "r"(addr))
#define LDMX2(r0, r1, addr) \
    asm volatile("ldmatrix.sync.aligned.m8n8.x2.shared.b16 {%0,%1}, [%2];" \
                 : "=r"(r0), "=r"(r1) : "r"(addr))
#define LDMX2T(r0, r1, addr) \
    asm volatile("ldmatrix.sync.aligned.m8n8.x2.trans.shared.b16 {%0,%1}, [%2];" \
                 : "=r"(r0), "=r"(r1) : "r"(addr))
#define MMA_BF16(c, a0, a1, a2, a3, b0, b1) \
    asm volatile("mma.sync.aligned.m16n8k16.row.col.f32.bf16.bf16.f32 " \
                 "{%0,%1,%2,%3}, {%4,%5,%6,%7}, {%8,%9}, {%0,%1,%2,%3};" \
                 : "+f"((c)[0]), "+f"((c)[1]), "+f"((c)[2]), "+f"((c)[3]) \
                 : "r"(a0), "r"(a1), "r"(a2), "r"(a3), "r"(b0), "r"(b1))

// ===================== LayerNorm (bf16 output) =====================
__global__ __launch_bounds__(256) void ln_kernel(const float* __restrict__ x,
                                                 const float* __restrict__ gamma,
                                                 const float* __restrict__ beta) {
    int row = blockIdx.x;
    int tid = threadIdx.x;
    const float* px = x + (size_t)row * CDIM;

    float4 a0 = *(const float4*)(px + tid * 4);
    float4 a1 = *(const float4*)(px + 1024 + tid * 4);

    float s = a0.x + a0.y + a0.z + a0.w + a1.x + a1.y + a1.z + a1.w;
    float q = a0.x*a0.x + a0.y*a0.y + a0.z*a0.z + a0.w*a0.w
            + a1.x*a1.x + a1.y*a1.y + a1.z*a1.z + a1.w*a1.w;

    #pragma unroll
    for (int off = 16; off; off >>= 1) {
        s += __shfl_xor_sync(0xffffffffu, s, off);
        q += __shfl_xor_sync(0xffffffffu, q, off);
    }
    __shared__ float sh[16];
    if ((tid & 31) == 0) { sh[tid >> 5] = s; sh[8 + (tid >> 5)] = q; }
    __syncthreads();
    float ts = 0.f, tq = 0.f;
    #pragma unroll
    for (int i = 0; i < 8; i++) { ts += sh[i]; tq += sh[8 + i]; }

    float mu   = ts * (1.f / 2048.f);
    float var  = tq * (1.f / 2048.f) - mu * mu;
    float rstd = rsqrtf(var + 1e-5f);

    float4 g0 = *(const float4*)(gamma + tid * 4);
    float4 g1 = *(const float4*)(gamma + 1024 + tid * 4);
    float4 b0 = *(const float4*)(beta + tid * 4);
    float4 b1 = *(const float4*)(beta + 1024 + tid * 4);

    __nv_bfloat16* po = g_nx + (size_t)row * CDIM;
    float o[8];
    o[0] = (a0.x - mu) * rstd * g0.x + b0.x;
    o[1] = (a0.y - mu) * rstd * g0.y + b0.y;
    o[2] = (a0.z - mu) * rstd * g0.z + b0.z;
    o[3] = (a0.w - mu) * rstd * g0.w + b0.w;
    o[4] = (a1.x - mu) * rstd * g1.x + b1.x;
    o[5] = (a1.y - mu) * rstd * g1.y + b1.y;
    o[6] = (a1.z - mu) * rstd * g1.z + b1.z;
    o[7] = (a1.w - mu) * rstd * g1.w + b1.w;
    *(__nv_bfloat162*)(po + 4 * tid)            = __floats2bfloat162_rn(o[0], o[1]);
    *(__nv_bfloat162*)(po + 4 * tid + 2)        = __floats2bfloat162_rn(o[2], o[3]);
    *(__nv_bfloat162*)(po + 1024 + 4 * tid)     = __floats2bfloat162_rn(o[4], o[5]);
    *(__nv_bfloat162*)(po + 1024 + 4 * tid + 2) = __floats2bfloat162_rn(o[6], o[7]);
}

// ===================== Weight transform: Wt[n][k] = bf16(W[k][n]) =====================
__global__ __launch_bounds__(256) void wcvt_kernel(
    const float* __restrict__ Wq, const float* __restrict__ Wk,
    const float* __restrict__ Wv, const float* __restrict__ Wo) {
    __shared__ float tile[32][33];
    int z = blockIdx.z;
    const float* W = (z == 0) ? Wq : (z == 1) ? Wk : (z == 2) ? Wv : Wo;
    __nv_bfloat16* Wt = (z == 0) ? g_wq : (z == 1) ? g_wk : (z == 2) ? g_wv : g_wo;

    int k0 = blockIdx.x * 32, n0 = blockIdx.y * 32;
    int c = threadIdx.x & 31, r = threadIdx.x >> 5;

    #pragma unroll
    for (int i = 0; i < 4; i++)
        tile[r + 8 * i][c] = W[(size_t)(k0 + r + 8 * i) * CDIM + n0 + c];
    __syncthreads();
    #pragma unroll
    for (int i = 0; i < 4; i++)
        Wt[(size_t)(n0 + r + 8 * i) * CDIM + k0 + c] = __float2bfloat16_rn(tile[c][r + 8 * i]);
}

// ===================== bf16 GEMM v5 (R12 mainloop) =====================
#define TG5_SMEM (6 * 16384)

template<int MODE>   // 0: QKV (q/k fp32, v bf16) ; 1: Wo (+bias+residual, fp32)
__global__ __launch_bounds__(256, 2) void tg5_kernel(
    const __nv_bfloat16* __restrict__ A,
    const __nv_bfloat16* __restrict__ B0, const __nv_bfloat16* __restrict__ B1,
    const __nv_bfloat16* __restrict__ B2,
    const float* __restrict__ c0, const float* __restrict__ c1, const float* __restrict__ c2,
    const float* __restrict__ R,
    float* __restrict__ Y0, float* __restrict__ Y1,
    __nv_bfloat16* __restrict__ Yb)
{
    const int N = CDIM;
    extern __shared__ char sm5[];
    uint32_t sb = (uint32_t)__cvta_generic_to_shared(sm5);

    int z = blockIdx.z;
    const __nv_bfloat16* Wt = (z == 0) ? B0 : (z == 1) ? B1 : B2;
    const float* bias = (z == 0) ? c0 : (z == 1) ? c1 : c2;
    float* Y = (z == 0) ? Y0 : Y1;

    int tid = threadIdx.x, lane = tid & 31, warp = tid >> 5;
    int bm = blockIdx.y * 128, bn = blockIdx.x * 128;

    int r = tid >> 3, cch = tid & 7;
    uint32_t swoff = (uint32_t)(r * 128 + ((cch ^ (r & 7)) << 4));
    const __nv_bfloat16* Ap = A  + (size_t)(bm + r) * CDIM + cch * 8;
    const __nv_bfloat16* Bp = Wt + (size_t)(bn + r) * CDIM + cch * 8;

    float c[4][4][4];
    #pragma unroll
    for (int mi = 0; mi < 4; mi++)
        #pragma unroll
        for (int ni = 0; ni < 4; ni++)
            #pragma unroll
            for (int q = 0; q < 4; q++) c[mi][ni][q] = 0.f;

    int wm = warp >> 2, wn = warp & 3;
    int mbase = wm * 64, nbase = wn * 32;
    int lq = lane >> 2, lr = lane & 3;
    int l7 = lane & 7, lh = (lane >> 3) & 1, lg = lane >> 4;

    auto issue = [&](int i, int s) {
        int k0 = i * 64;
        uint32_t da = sb + (uint32_t)s * 16384 + swoff;
        uint32_t db = sb + 49152u + (uint32_t)s * 16384 + swoff;
        #pragma unroll
        for (int it = 0; it < 4; it++) {
            cp_async16(da + it * 4096, Ap + (size_t)(it * 32) * CDIM + k0);
            cp_async16(db + it * 4096, Bp + (size_t)(it * 32) * CDIM + k0);
        }
        CP_COMMIT();
    };

    issue(0, 0);
    issue(1, 1);

    uint32_t arow = (uint32_t)(mbase + lh * 8 + l7);
    uint32_t brow = (uint32_t)(nbase + l7);

    const int NITER = CDIM / 64;   // 32
    for (int i = 0; i < NITER; ++i) {
        int s = i - (i / 3) * 3;
        if (i == NITER - 1) { CP_WAIT(0); } else { CP_WAIT(1); }
        __syncthreads();
        if (i + 2 < NITER) issue(i + 2, (i + 2) % 3);

        uint32_t Ab = sb + (uint32_t)s * 16384;
        uint32_t Bb = sb + 49152u + (uint32_t)s * 16384;

        #pragma unroll
        for (int kt = 0; kt < 4; kt++) {
            uint32_t b[4][2];
            uint32_t bch = (uint32_t)(((2 * kt + lh) ^ l7) << 4);
            #pragma unroll
            for (int ni = 0; ni < 4; ni++)
                LDMX2(b[ni][0], b[ni][1], Bb + (brow + ni * 8) * 128 + bch);
            uint32_t ach = (uint32_t)(((2 * kt + lg) ^ l7) << 4);
            #pragma unroll
            for (int mi = 0; mi < 4; mi++) {
                uint32_t a0, a1, a2, a3;
                LDMX4(a0, a1, a2, a3, Ab + (arow + mi * 16) * 128 + ach);
                #pragma unroll
                for (int ni = 0; ni < 4; ni++)
                    MMA_BF16(c[mi][ni], a0, a1, a2, a3, b[ni][0], b[ni][1]);
            }
        }
    }

    #pragma unroll
    for (int mi = 0; mi < 4; mi++) {
        int r0 = bm + mbase + mi * 16 + lq;
        #pragma unroll
        for (int ni = 0; ni < 4; ni++) {
            int cb = bn + nbase + ni * 8 + 2 * lr;
            float bx = bias[cb], by = bias[cb + 1];
            float2 v0 = make_float2(c[mi][ni][0] + bx, c[mi][ni][1] + by);
            float2 v1 = make_float2(c[mi][ni][2] + bx, c[mi][ni][3] + by);
            if (MODE == 1) {
                float2 r0v = *(const float2*)(R + (size_t)r0 * N + cb);
                float2 r1v = *(const float2*)(R + (size_t)(r0 + 8) * N + cb);
                v0.x += r0v.x; v0.y += r0v.y;
                v1.x += r1v.x; v1.y += r1v.y;
                *(float2*)(Y + (size_t)r0 * N + cb)       = v0;
                *(float2*)(Y + (size_t)(r0 + 8) * N + cb) = v1;
            } else if (z == 2) {   // v: straight to bf16
                *(__nv_bfloat162*)(Yb + (size_t)r0 * N + cb) =
                    __floats2bfloat162_rn(v0.x, v0.y);
                *(__nv_bfloat162*)(Yb + (size_t)(r0 + 8) * N + cb) =
                    __floats2bfloat162_rn(v1.x, v1.y);
            } else {               // q/k: fp32, rope rounds later
                *(float2*)(Y + (size_t)r0 * N + cb)       = v0;
                *(float2*)(Y + (size_t)(r0 + 8) * N + cb) = v1;
            }
        }
    }
}

// ===================== RoPE: fp32 q/k in -> bf16 out =====================
__global__ __launch_bounds__(256) void rope_kernel() {
    int row = blockIdx.x;
    const float* bufi = (blockIdx.y == 0) ? g_q : g_k;
    __nv_bfloat16* bufo = (blockIdx.y == 0) ? g_qb : g_kb;
    int t = row & (TSEQ - 1);

    __shared__ float cs[64], sn[64];
    if (threadIdx.x < 64) {
        float inv = powf(10000.f, -(float)threadIdx.x / 64.f);
        float ang = (float)t * inv;
        cs[threadIdx.x] = cosf(ang);
        sn[threadIdx.x] = sinf(ang);
    }
    __syncthreads();

    const float* p = bufi + (size_t)row * CDIM;
    __nv_bfloat16* o = bufo + (size_t)row * CDIM;
    for (int idx = threadIdx.x; idx < NHEAD * 64; idx += 256) {
        int h = idx >> 6, f = idx & 63;
        float a = p[h * 128 + f];
        float b = p[h * 128 + 64 + f];
        o[h * 128 + f]      = __float2bfloat16_rn(a * cs[f] - b * sn[f]);
        o[h * 128 + 64 + f] = __float2bfloat16_rn(b * cs[f] + a * sn[f]);
    }
}

// ===================== Flash attention v4: bf16 m16n8k16 + ldmatrix ===============
// grid (T/128 rev, H, B), 256 thr, warp owns 16 q-rows. Q[128][256B] SW128,
// K dbl-buffered [64][256B], V [64][256B] (ldmatrix.trans), P bf16 [128][128B].
#define FLASHB_SMEM 98304

__global__ __launch_bounds__(256, 1) void flash_bf_kernel() {
    extern __shared__ char smf[];
    uint32_t sb = (uint32_t)__cvta_generic_to_shared(smf);
    uint32_t Qb = sb, K0b = sb + 32768u, K1b = sb + 49152u;
    uint32_t Vb = sb + 65536u, Pb = sb + 81920u;
    char* Pp = smf + 81920;

    int qb = gridDim.x - 1 - blockIdx.x;
    int h = blockIdx.y, b = blockIdx.z;
    int tid = threadIdx.x, lane = tid & 31, warp = tid >> 5;
    int lq = lane >> 2, lr = lane & 3;
    int l7 = lane & 7, lh = (lane >> 3) & 1, lg = lane >> 4;

    size_t base = ((size_t)b * TSEQ) * CDIM + (size_t)h * HDIM;

    // Q tile: 128 rows x 16 granules (16B), SW128 per 128B half
    #pragma unroll
    for (int it = 0; it < 8; it++) {
        int gi = tid + it * 256;
        int r = gi >> 4, g = gi & 15;
        cp_async16(Qb + (uint32_t)(r * 256 + (g >> 3) * 128 + (((g & 7) ^ (r & 7)) << 4)),
                   g_qb + base + (size_t)(qb * 128 + r) * CDIM + g * 8);
    }
    CP_COMMIT();

    // prologue K(0)
    #pragma unroll
    for (int it = 0; it < 4; it++) {
        int gi = tid + it * 256;
        int r = gi >> 4, g = gi & 15;
        cp_async16(K0b + (uint32_t)(r * 256 + (g >> 3) * 128 + (((g & 7) ^ (r & 7)) << 4)),
                   g_kb + base + (size_t)r * CDIM + g * 8);
    }
    CP_COMMIT();

    float m0 = -1e30f, m1 = -1e30f, l0 = 0.f, l1 = 0.f;
    float O[16][4];
    #pragma unroll
    for (int nt = 0; nt < 16; nt++)
        #pragma unroll
        for (int r = 0; r < 4; r++) O[nt][r] = 0.f;

    const float scale = 0.08838834764831845f;
    int srow = warp * 16 + lq;                 // softmax row (lo); +8 = hi
    int grow0 = qb * 128 + srow;
    uint32_t frow = (uint32_t)(warp * 16 + lh * 8 + l7);   // ldmatrix A row
    int nkb = 2 * (qb + 1);

    for (int kb = 0; kb < nkb; kb++) {
        __syncthreads();   // PV(kb-1) done: V + K target free

        // stream V(kb)
        #pragma unroll
        for (int it = 0; it < 4; it++) {
            int gi = tid + it * 256;
            int r = gi >> 4, g = gi & 15;
            cp_async16(Vb + (uint32_t)(r * 256 + (g >> 3) * 128 + (((g & 7) ^ (r & 7)) << 4)),
                       g_vb + base + (size_t)(kb * 64 + r) * CDIM + g * 8);
        }
        CP_COMMIT();

        bool more = (kb + 1 < nkb);
        if (more) {   // stream K(kb+1)
            uint32_t ka = ((kb + 1) & 1) ? K1b : K0b;
            #pragma unroll
            for (int it = 0; it < 4; it++) {
                int gi = tid + it * 256;
                int r = gi >> 4, g = gi & 15;
                cp_async16(ka + (uint32_t)(r * 256 + (g >> 3) * 128 + (((g & 7) ^ (r & 7)) << 4)),
                           g_kb + base + (size_t)((kb + 1) * 64 + r) * CDIM + g * 8);
            }
            CP_COMMIT();
        }

        if (more) { CP_WAIT(2); } else { CP_WAIT(1); }   // K(kb) (and Q) ready
        __syncthreads();

        uint32_t Kc = (kb & 1) ? K1b : K0b;

        // ---- S = Q K^T : 8 k16 steps, warp 16x64 ----
        float s[8][4];
        #pragma unroll
        for (int nt = 0; nt < 8; nt++)
            #pragma unroll
            for (int r = 0; r < 4; r++) s[nt][r] = 0.f;

        #pragma unroll
        for (int kt = 0; kt < 8; kt++) {
            int ga = kt * 2 + lg;
            uint32_t a0, a1, a2, a3;
            LDMX4(a0, a1, a2, a3,
                  Qb + frow * 256 + (uint32_t)((ga >> 3) * 128 + (((ga & 7) ^ (frow & 7)) << 4)));
            int gb = kt * 2 + lh;
            #pragma unroll
            for (int nt = 0; nt < 8; nt++) {
                uint32_t krow = (uint32_t)(nt * 8 + l7);
                uint32_t b0, b1;
                LDMX2(b0, b1,
                      Kc + krow * 256 + (uint32_t)((gb >> 3) * 128 + (((gb & 7) ^ (krow & 7)) << 4)));
                MMA_BF16(s[nt], a0, a1, a2, a3, b0, b1);
            }
        }

        // ---- scale + causal mask + online softmax (fp32) ----
        bool needmask = (kb * 64 + 63 > qb * 128 + warp * 16);
        float t0 = -1e30f, t1 = -1e30f;
        #pragma unroll
        for (int nt = 0; nt < 8; nt++) {
            if (needmask) {
                int cc0 = kb * 64 + nt * 8 + 2 * lr;
                s[nt][0] = (cc0     <= grow0)     ? s[nt][0] * scale : -1e30f;
                s[nt][1] = (cc0 + 1 <= grow0)     ? s[nt][1] * scale : -1e30f;
                s[nt][2] = (cc0     <= grow0 + 8) ? s[nt][2] * scale : -1e30f;
                s[nt][3] = (cc0 + 1 <= grow0 + 8) ? s[nt][3] * scale : -1e30f;
            } else {
                s[nt][0] *= scale; s[nt][1] *= scale;
                s[nt][2] *= scale; s[nt][3] *= scale;
            }
            t0 = fmaxf(t0, fmaxf(s[nt][0], s[nt][1]));
            t1 = fmaxf(t1, fmaxf(s[nt][2], s[nt][3]));
        }
        t0 = fmaxf(t0, __shfl_xor_sync(0xffffffffu, t0, 1));
        t0 = fmaxf(t0, __shfl_xor_sync(0xffffffffu, t0, 2));
        t1 = fmaxf(t1, __shfl_xor_sync(0xffffffffu, t1, 1));
        t1 = fmaxf(t1, __shfl_xor_sync(0xffffffffu, t1, 2));

        float mn0 = fmaxf(m0, t0), mn1 = fmaxf(m1, t1);
        float al0 = __expf(m0 - mn0), al1 = __expf(m1 - mn1);
        float rs0 = 0.f, rs1 = 0.f;
        int pr0 = srow, pr1 = srow + 8;
        #pragma unroll
        for (int nt = 0; nt < 8; nt++) {
            __nv_bfloat162 h0 = __floats2bfloat162_rn(__expf(s[nt][0] - mn0),
                                                      __expf(s[nt][1] - mn0));
            __nv_bfloat162 h1 = __floats2bfloat162_rn(__expf(s[nt][2] - mn1),
                                                      __expf(s[nt][3] - mn1));
            rs0 += __bfloat162float(h0.x) + __bfloat162float(h0.y);
            rs1 += __bfloat162float(h1.x) + __bfloat162float(h1.y);
            *(__nv_bfloat162*)(Pp + pr0 * 128 + ((nt ^ (pr0 & 7)) << 4) + 4 * lr) = h0;
            *(__nv_bfloat162*)(Pp + pr1 * 128 + ((nt ^ (pr1 & 7)) << 4) + 4 * lr) = h1;
        }
        rs0 += __shfl_xor_sync(0xffffffffu, rs0, 1);
        rs0 += __shfl_xor_sync(0xffffffffu, rs0, 2);
        rs1 += __shfl_xor_sync(0xffffffffu, rs1, 1);
        rs1 += __shfl_xor_sync(0xffffffffu, rs1, 2);

        l0 = l0 * al0 + rs0;  l1 = l1 * al1 + rs1;
        m0 = mn0;             m1 = mn1;
        #pragma unroll
        for (int nt = 0; nt < 16; nt++) {
            O[nt][0] *= al0; O[nt][1] *= al0;
            O[nt][2] *= al1; O[nt][3] *= al1;
        }
        __syncwarp();   // P warp-private: stores before ldmatrix

        if (more) { CP_WAIT(1); } else { CP_WAIT(0); }   // V(kb) ready
        __syncthreads();

        // ---- O += P V : 4 k16 steps, warp 16x128; V via ldmatrix.trans ----
        #pragma unroll
        for (int kt = 0; kt < 4; kt++) {
            int ga = kt * 2 + lg;   // P granule 0..7
            uint32_t a0, a1, a2, a3;
            LDMX4(a0, a1, a2, a3,
                  Pb + frow * 128 + (uint32_t)(((ga ^ (frow & 7)) << 4)));
            uint32_t vrow = (uint32_t)(kt * 16 + lh * 8 + l7);   // V seq row
            uint32_t vbase = Vb + vrow * 256;
            uint32_t vsw = (vrow & 7) << 4;
            #pragma unroll
            for (int nt = 0; nt < 16; nt++) {
                uint32_t b0, b1;
                LDMX2T(b0, b1,
                       vbase + (uint32_t)((nt >> 3) * 128) + ((((uint32_t)(nt & 7) << 4) ^ vsw)));
                MMA_BF16(O[nt], a0, a1, a2, a3, b0, b1);
            }
        }
    }

    // ---- epilogue: normalize, write bf16 (feeds Wo GEMM) ----
    float inv0 = 1.f / l0, inv1 = 1.f / l1;
    size_t row0 = (size_t)b * TSEQ + grow0;
    #pragma unroll
    for (int nt = 0; nt < 16; nt++) {
        int col = h * HDIM + nt * 8 + 2 * lr;
        *(__nv_bfloat162*)(g_att + row0 * CDIM + col) =
            __floats2bfloat162_rn(O[nt][0] * inv0, O[nt][1] * inv0);
        *(__nv_bfloat162*)(g_att + (row0 + 8) * CDIM + col) =
            __floats2bfloat162_rn(O[nt][2] * inv1, O[nt][3] * inv1);
    }
}

// ===================== launch =====================
extern "C" void kernel_launch(void* const* d_in, const int* in_sizes, int n_in,
                              void* d_out, int out_size) {
    const float* x    = (const float*)d_in[0];
    const float* ln_g = (const float*)d_in[1];
    const float* ln_b = (const float*)d_in[2];
    const float* Wq   = (const float*)d_in[3];
    const float* bq   = (const float*)d_in[4];
    const float* Wk   = (const float*)d_in[5];
    const float* bk   = (const float*)d_in[6];
    const float* Wv   = (const float*)d_in[7];
    const float* bv   = (const float*)d_in[8];
    const float* Wo   = (const float*)d_in[9];
    const float* bo   = (const float*)d_in[10];
    float* out = (float*)d_out;

    __nv_bfloat16 *nx, *ap, *wq, *wk, *wv, *wo, *vb;
    float *qp, *kp;
    cudaGetSymbolAddress((void**)&nx, g_nx);
    cudaGetSymbolAddress((void**)&qp, g_q);
    cudaGetSymbolAddress((void**)&kp, g_k);
    cudaGetSymbolAddress((void**)&vb, g_vb);
    cudaGetSymbolAddress((void**)&ap, g_att);
    cudaGetSymbolAddress((void**)&wq, g_wq);
    cudaGetSymbolAddress((void**)&wk, g_wk);
    cudaGetSymbolAddress((void**)&wv, g_wv);
    cudaGetSymbolAddress((void**)&wo, g_wo);

    cudaFuncSetAttribute(flash_bf_kernel, cudaFuncAttributeMaxDynamicSharedMemorySize, FLASHB_SMEM);
    cudaFuncSetAttribute(tg5_kernel<0>, cudaFuncAttributeMaxDynamicSharedMemorySize, TG5_SMEM);
    cudaFuncSetAttribute(tg5_kernel<1>, cudaFuncAttributeMaxDynamicSharedMemorySize, TG5_SMEM);

    ln_kernel<<<BTOT, 256>>>(x, ln_g, ln_b);
    wcvt_kernel<<<dim3(64, 64, 4), 256>>>(Wq, Wk, Wv, Wo);

    // fused Q/K/V projections (bf16): q,k fp32 out; v bf16 out
    tg5_kernel<0><<<dim3(16, 64, 3), 256, TG5_SMEM>>>(
        nx, wq, wk, wv, bq, bk, bv, nullptr, qp, kp, vb);

    rope_kernel<<<dim3(BTOT, 2), 256>>>();

    flash_bf_kernel<<<dim3(TSEQ / 128, NHEAD, 4), 256, FLASHB_SMEM>>>();

    // output projection + residual (bf16 operands, fp32 out)
    tg5_kernel<1><<<dim3(16, 64, 1), 256, TG5_SMEM>>>(
        ap, wo, wo, wo, bo, bo, bo, x, out, out, nullptr);
}

// round 15
// speedup vs baseline: 2.3535x; 1.0289x over previous
#include <cuda_runtime.h>
#include <cuda_bf16.h>
#include <math.h>
#include <stdint.h>

#define BTOT 8192      // B*T rows
#define CDIM 2048      // channels
#define TSEQ 2048      // sequence length
#define NHEAD 16
#define HDIM 128

// -------- scratch (device globals; allocation-free) --------
__device__ __nv_bfloat16 g_nx [BTOT * CDIM];   // LN out, bf16
__device__ __nv_bfloat16 g_qb [BTOT * CDIM];   // q (rope applied), bf16
__device__ __nv_bfloat16 g_kb [BTOT * CDIM];   // k (rope applied), bf16
__device__ __nv_bfloat16 g_vb [BTOT * CDIM];   // v, bf16
__device__ __nv_bfloat16 g_att[BTOT * CDIM];   // flash out, bf16
__device__ __nv_bfloat16 g_wq [CDIM * CDIM];   // Wt[n][k], bf16
__device__ __nv_bfloat16 g_wk [CDIM * CDIM];
__device__ __nv_bfloat16 g_wv [CDIM * CDIM];
__device__ __nv_bfloat16 g_wo [CDIM * CDIM];
__device__ float g_rope[TSEQ * 128];           // row t: [0..63]=cos, [64..127]=sin

__device__ __forceinline__ void cp_async16(uint32_t dst_smem, const void* src) {
    asm volatile("cp.async.cg.shared.global [%0], [%1], 16;\n"
                 :: "r"(dst_smem), "l"(src));
}
#define CP_COMMIT() asm volatile("cp.async.commit_group;\n" ::: "memory")
#define CP_WAIT(n)  asm volatile("cp.async.wait_group %0;\n" :: "n"(n) : "memory")

#define LDMX4(r0, r1, r2, r3, addr) \
    asm volatile("ldmatrix.sync.aligned.m8n8.x4.shared.b16 {%0,%1,%2,%3}, [%4];" \
                 : "=r"(r0), "=r"(r1), "=r"(r2), "=r"(r3) : "r"(addr))
#define LDMX2(r0, r1, addr) \
    asm volatile("ldmatrix.sync.aligned.m8n8.x2.shared.b16 {%0,%1}, [%2];" \
                 : "=r"(r0), "=r"(r1) : "r"(addr))
#define LDMX2T(r0, r1, addr) \
    asm volatile("ldmatrix.sync.aligned.m8n8.x2.trans.shared.b16 {%0,%1}, [%2];" \
                 : "=r"(r0), "=r"(r1) : "r"(addr))
#define MMA_BF16(c, a0, a1, a2, a3, b0, b1) \
    asm volatile("mma.sync.aligned.m16n8k16.row.col.f32.bf16.bf16.f32 " \
                 "{%0,%1,%2,%3}, {%4,%5,%6,%7}, {%8,%9}, {%0,%1,%2,%3};" \
                 : "+f"((c)[0]), "+f"((c)[1]), "+f"((c)[2]), "+f"((c)[3]) \
                 : "r"(a0), "r"(a1), "r"(a2), "r"(a3), "r"(b0), "r"(b1))

// ===================== Prep: LN + weight transform + rope table =====================
// blocks [0,8192): LN rows -> bf16 ; [8192,24576): Wt[n][k]=bf16(W[k][n]) ;
// [24576,25600): rope table (2 t-rows per block)
__global__ __launch_bounds__(256) void prep_kernel(
    const float* __restrict__ x,
    const float* __restrict__ gamma, const float* __restrict__ beta,
    const float* __restrict__ Wq, const float* __restrict__ Wk,
    const float* __restrict__ Wv, const float* __restrict__ Wo) {
    __shared__ float sh[16];
    __shared__ float tile[32][33];
    int bx = blockIdx.x, tid = threadIdx.x;

    if (bx < 8192) {                      // ---- LayerNorm ----
        const float* px = x + (size_t)bx * CDIM;
        float4 a0 = *(const float4*)(px + tid * 4);
        float4 a1 = *(const float4*)(px + 1024 + tid * 4);

        float s = a0.x + a0.y + a0.z + a0.w + a1.x + a1.y + a1.z + a1.w;
        float q = a0.x*a0.x + a0.y*a0.y + a0.z*a0.z + a0.w*a0.w
                + a1.x*a1.x + a1.y*a1.y + a1.z*a1.z + a1.w*a1.w;
        #pragma unroll
        for (int off = 16; off; off >>= 1) {
            s += __shfl_xor_sync(0xffffffffu, s, off);
            q += __shfl_xor_sync(0xffffffffu, q, off);
        }
        if ((tid & 31) == 0) { sh[tid >> 5] = s; sh[8 + (tid >> 5)] = q; }
        __syncthreads();
        float ts = 0.f, tq = 0.f;
        #pragma unroll
        for (int i = 0; i < 8; i++) { ts += sh[i]; tq += sh[8 + i]; }

        float mu   = ts * (1.f / 2048.f);
        float var  = tq * (1.f / 2048.f) - mu * mu;
        float rstd = rsqrtf(var + 1e-5f);

        float4 g0 = *(const float4*)(gamma + tid * 4);
        float4 g1 = *(const float4*)(gamma + 1024 + tid * 4);
        float4 b0 = *(const float4*)(beta + tid * 4);
        float4 b1 = *(const float4*)(beta + 1024 + tid * 4);

        __nv_bfloat16* po = g_nx + (size_t)bx * CDIM;
        float o[8];
        o[0] = (a0.x - mu) * rstd * g0.x + b0.x;
        o[1] = (a0.y - mu) * rstd * g0.y + b0.y;
        o[2] = (a0.z - mu) * rstd * g0.z + b0.z;
        o[3] = (a0.w - mu) * rstd * g0.w + b0.w;
        o[4] = (a1.x - mu) * rstd * g1.x + b1.x;
        o[5] = (a1.y - mu) * rstd * g1.y + b1.y;
        o[6] = (a1.z - mu) * rstd * g1.z + b1.z;
        o[7] = (a1.w - mu) * rstd * g1.w + b1.w;
        *(__nv_bfloat162*)(po + 4 * tid)            = __floats2bfloat162_rn(o[0], o[1]);
        *(__nv_bfloat162*)(po + 4 * tid + 2)        = __floats2bfloat162_rn(o[2], o[3]);
        *(__nv_bfloat162*)(po + 1024 + 4 * tid)     = __floats2bfloat162_rn(o[4], o[5]);
        *(__nv_bfloat162*)(po + 1024 + 4 * tid + 2) = __floats2bfloat162_rn(o[6], o[7]);
    } else if (bx < 24576) {              // ---- weight transform ----
        int idx = bx - 8192;
        int z = idx >> 12, rem = idx & 4095;
        int k0 = (rem >> 6) * 32, n0 = (rem & 63) * 32;
        const float* W = (z == 0) ? Wq : (z == 1) ? Wk : (z == 2) ? Wv : Wo;
        __nv_bfloat16* Wt = (z == 0) ? g_wq : (z == 1) ? g_wk : (z == 2) ? g_wv : g_wo;

        int c = tid & 31, r = tid >> 5;
        #pragma unroll
        for (int i = 0; i < 4; i++)
            tile[r + 8 * i][c] = W[(size_t)(k0 + r + 8 * i) * CDIM + n0 + c];
        __syncthreads();
        #pragma unroll
        for (int i = 0; i < 4; i++)
            Wt[(size_t)(n0 + r + 8 * i) * CDIM + k0 + c] =
                __float2bfloat16_rn(tile[c][r + 8 * i]);
    } else {                              // ---- rope table ----
        int t = (bx - 24576) * 2 + (tid >> 7);
        int c = tid & 127, f = c & 63;
        float inv = powf(10000.f, -(float)f / 64.f);
        float ang = (float)t * inv;
        g_rope[t * 128 + c] = (c < 64) ? cosf(ang) : sinf(ang);
    }
}

// ===================== bf16 GEMM v6: R13 mainloop + split-half warp cols ==========
// Warp wn owns cols {wn*16..+15} U {wn*16+64..+79}: rotation pairs (f,f+64) are
// thread-local (ni <-> ni+2) -> rope fused in registers, no staging, no syncs.
#define TG5_SMEM (6 * 16384)

template<int MODE>   // 0: QKV (rope for z<2, all bf16 out) ; 1: Wo (+bias+res, fp32)
__global__ __launch_bounds__(256, 2) void tg5_kernel(
    const __nv_bfloat16* __restrict__ A,
    const __nv_bfloat16* __restrict__ B0, const __nv_bfloat16* __restrict__ B1,
    const __nv_bfloat16* __restrict__ B2,
    const float* __restrict__ c0, const float* __restrict__ c1, const float* __restrict__ c2,
    const float* __restrict__ R,
    float* __restrict__ Yf,
    __nv_bfloat16* __restrict__ Yb0, __nv_bfloat16* __restrict__ Yb1,
    __nv_bfloat16* __restrict__ Yb2)
{
    const int N = CDIM;
    extern __shared__ char sm5[];
    uint32_t sb = (uint32_t)__cvta_generic_to_shared(sm5);

    int z = blockIdx.z;
    const __nv_bfloat16* Wt = (z == 0) ? B0 : (z == 1) ? B1 : B2;
    const float* bias = (z == 0) ? c0 : (z == 1) ? c1 : c2;

    int tid = threadIdx.x, lane = tid & 31, warp = tid >> 5;
    int bm = blockIdx.y * 128, bn = blockIdx.x * 128;

    int r = tid >> 3, cch = tid & 7;
    uint32_t swoff = (uint32_t)(r * 128 + ((cch ^ (r & 7)) << 4));
    const __nv_bfloat16* Ap = A  + (size_t)(bm + r) * CDIM + cch * 8;
    const __nv_bfloat16* Bp = Wt + (size_t)(bn + r) * CDIM + cch * 8;

    float c[4][4][4];
    #pragma unroll
    for (int mi = 0; mi < 4; mi++)
        #pragma unroll
        for (int ni = 0; ni < 4; ni++)
            #pragma unroll
            for (int q = 0; q < 4; q++) c[mi][ni][q] = 0.f;

    int wm = warp >> 2, wn = warp & 3;
    int mbase = wm * 64;
    int lq = lane >> 2, lr = lane & 3;
    int l7 = lane & 7, lh = (lane >> 3) & 1, lg = lane >> 4;

    // split-half column base per n-tile: {0,8,64,72} + wn*16
    int colof[4];
    #pragma unroll
    for (int ni = 0; ni < 4; ni++)
        colof[ni] = wn * 16 + (ni & 1) * 8 + (ni >> 1) * 64;

    auto issue = [&](int i, int s) {
        int k0 = i * 64;
        uint32_t da = sb + (uint32_t)s * 16384 + swoff;
        uint32_t db = sb + 49152u + (uint32_t)s * 16384 + swoff;
        #pragma unroll
        for (int it = 0; it < 4; it++) {
            cp_async16(da + it * 4096, Ap + (size_t)(it * 32) * CDIM + k0);
            cp_async16(db + it * 4096, Bp + (size_t)(it * 32) * CDIM + k0);
        }
        CP_COMMIT();
    };

    issue(0, 0);
    issue(1, 1);

    uint32_t arow = (uint32_t)(mbase + lh * 8 + l7);

    const int NITER = CDIM / 64;   // 32
    for (int i = 0; i < NITER; ++i) {
        int s = i - (i / 3) * 3;
        if (i == NITER - 1) { CP_WAIT(0); } else { CP_WAIT(1); }
        __syncthreads();
        if (i + 2 < NITER) issue(i + 2, (i + 2) % 3);

        uint32_t Ab = sb + (uint32_t)s * 16384;
        uint32_t Bb = sb + 49152u + (uint32_t)s * 16384;

        #pragma unroll
        for (int kt = 0; kt < 4; kt++) {
            uint32_t b[4][2];
            uint32_t bch = (uint32_t)(((2 * kt + lh) ^ l7) << 4);
            #pragma unroll
            for (int ni = 0; ni < 4; ni++)
                LDMX2(b[ni][0], b[ni][1], Bb + (uint32_t)(colof[ni] + l7) * 128 + bch);
            uint32_t ach = (uint32_t)(((2 * kt + lg) ^ l7) << 4);
            #pragma unroll
            for (int mi = 0; mi < 4; mi++) {
                uint32_t a0, a1, a2, a3;
                LDMX4(a0, a1, a2, a3, Ab + (arow + mi * 16) * 128 + ach);
                #pragma unroll
                for (int ni = 0; ni < 4; ni++)
                    MMA_BF16(c[mi][ni], a0, a1, a2, a3, b[ni][0], b[ni][1]);
            }
        }
    }

    if (MODE == 0) {
        __nv_bfloat16* Yb = (z == 0) ? Yb0 : (z == 1) ? Yb1 : Yb2;
        #pragma unroll
        for (int mi = 0; mi < 4; mi++) {
            int r0 = bm + mbase + mi * 16 + lq;
            if (z < 2) {
                // rope in registers: ni pair (p, p+2) = cols (f, f+64)
                int t0 = r0 & (TSEQ - 1), t1 = (r0 + 8) & (TSEQ - 1);
                #pragma unroll
                for (int p = 0; p < 2; p++) {
                    int f = colof[p] + 2 * lr;              // 0..127 (even)
                    float bx  = bias[bn + f],      by  = bias[bn + f + 1];
                    float bx2 = bias[bn + f + 64], by2 = bias[bn + f + 65];
                    float2 cs0 = *(const float2*)&g_rope[t0 * 128 + f];
                    float2 sn0 = *(const float2*)&g_rope[t0 * 128 + 64 + f];
                    float2 cs1 = *(const float2*)&g_rope[t1 * 128 + f];
                    float2 sn1 = *(const float2*)&g_rope[t1 * 128 + 64 + f];
                    // row r0
                    float a0 = c[mi][p][0] + bx,      a1 = c[mi][p][1] + by;
                    float q0 = c[mi][p + 2][0] + bx2, q1 = c[mi][p + 2][1] + by2;
                    *(__nv_bfloat162*)(Yb + (size_t)r0 * N + bn + f) =
                        __floats2bfloat162_rn(a0 * cs0.x - q0 * sn0.x,
                                              a1 * cs0.y - q1 * sn0.y);
                    *(__nv_bfloat162*)(Yb + (size_t)r0 * N + bn + f + 64) =
                        __floats2bfloat162_rn(q0 * cs0.x + a0 * sn0.x,
                                              q1 * cs0.y + a1 * sn0.y);
                    // row r0+8
                    float a2 = c[mi][p][2] + bx,      a3 = c[mi][p][3] + by;
                    float q2 = c[mi][p + 2][2] + bx2, q3 = c[mi][p + 2][3] + by2;
                    *(__nv_bfloat162*)(Yb + (size_t)(r0 + 8) * N + bn + f) =
                        __floats2bfloat162_rn(a2 * cs1.x - q2 * sn1.x,
                                              a3 * cs1.y - q3 * sn1.y);
                    *(__nv_bfloat162*)(Yb + (size_t)(r0 + 8) * N + bn + f + 64) =
                        __floats2bfloat162_rn(q2 * cs1.x + a2 * sn1.x,
                                              q3 * cs1.y + a3 * sn1.y);
                }
            } else {
                #pragma unroll
                for (int ni = 0; ni < 4; ni++) {
                    int cb = bn + colof[ni] + 2 * lr;
                    float bx = bias[cb], by = bias[cb + 1];
                    *(__nv_bfloat162*)(Yb + (size_t)r0 * N + cb) =
                        __floats2bfloat162_rn(c[mi][ni][0] + bx, c[mi][ni][1] + by);
                    *(__nv_bfloat162*)(Yb + (size_t)(r0 + 8) * N + cb) =
                        __floats2bfloat162_rn(c[mi][ni][2] + bx, c[mi][ni][3] + by);
                }
            }
        }
    } else {
        #pragma unroll
        for (int mi = 0; mi < 4; mi++) {
            int r0 = bm + mbase + mi * 16 + lq;
            #pragma unroll
            for (int ni = 0; ni < 4; ni++) {
                int cb = bn + colof[ni] + 2 * lr;
                float bx = bias[cb], by = bias[cb + 1];
                float2 v0 = make_float2(c[mi][ni][0] + bx, c[mi][ni][1] + by);
                float2 v1 = make_float2(c[mi][ni][2] + bx, c[mi][ni][3] + by);
                float2 r0v = *(const float2*)(R + (size_t)r0 * N + cb);
                float2 r1v = *(const float2*)(R + (size_t)(r0 + 8) * N + cb);
                v0.x += r0v.x; v0.y += r0v.y;
                v1.x += r1v.x; v1.y += r1v.y;
                *(float2*)(Yf + (size_t)r0 * N + cb)       = v0;
                *(float2*)(Yf + (size_t)(r0 + 8) * N + cb) = v1;
            }
        }
    }
}

// ===================== Flash attention v4 (unchanged from R13) =====================
#define FLASHB_SMEM 98304

__global__ __launch_bounds__(256, 1) void flash_bf_kernel() {
    extern __shared__ char smf[];
    uint32_t sb = (uint32_t)__cvta_generic_to_shared(smf);
    uint32_t Qb = sb, K0b = sb + 32768u, K1b = sb + 49152u;
    uint32_t Vb = sb + 65536u, Pb = sb + 81920u;
    char* Pp = smf + 81920;

    int qb = gridDim.x - 1 - blockIdx.x;
    int h = blockIdx.y, b = blockIdx.z;
    int tid = threadIdx.x, lane = tid & 31, warp = tid >> 5;
    int lq = lane >> 2, lr = lane & 3;
    int l7 = lane & 7, lh = (lane >> 3) & 1, lg = lane >> 4;

    size_t base = ((size_t)b * TSEQ) * CDIM + (size_t)h * HDIM;

    #pragma unroll
    for (int it = 0; it < 8; it++) {
        int gi = tid + it * 256;
        int r = gi >> 4, g = gi & 15;
        cp_async16(Qb + (uint32_t)(r * 256 + (g >> 3) * 128 + (((g & 7) ^ (r & 7)) << 4)),
                   g_qb + base + (size_t)(qb * 128 + r) * CDIM + g * 8);
    }
    CP_COMMIT();

    #pragma unroll
    for (int it = 0; it < 4; it++) {
        int gi = tid + it * 256;
        int r = gi >> 4, g = gi & 15;
        cp_async16(K0b + (uint32_t)(r * 256 + (g >> 3) * 128 + (((g & 7) ^ (r & 7)) << 4)),
                   g_kb + base + (size_t)r * CDIM + g * 8);
    }
    CP_COMMIT();

    float m0 = -1e30f, m1 = -1e30f, l0 = 0.f, l1 = 0.f;
    float O[16][4];
    #pragma unroll
    for (int nt = 0; nt < 16; nt++)
        #pragma unroll
        for (int r = 0; r < 4; r++) O[nt][r] = 0.f;

    const float scale = 0.08838834764831845f;
    int srow = warp * 16 + lq;
    int grow0 = qb * 128 + srow;
    uint32_t frow = (uint32_t)(warp * 16 + lh * 8 + l7);
    int nkb = 2 * (qb + 1);

    for (int kb = 0; kb < nkb; kb++) {
        __syncthreads();

        #pragma unroll
        for (int it = 0; it < 4; it++) {
            int gi = tid + it * 256;
            int r = gi >> 4, g = gi & 15;
            cp_async16(Vb + (uint32_t)(r * 256 + (g >> 3) * 128 + (((g & 7) ^ (r & 7)) << 4)),
                       g_vb + base + (size_t)(kb * 64 + r) * CDIM + g * 8);
        }
        CP_COMMIT();

        bool more = (kb + 1 < nkb);
        if (more) {
            uint32_t ka = ((kb + 1) & 1) ? K1b : K0b;
            #pragma unroll
            for (int it = 0; it < 4; it++) {
                int gi = tid + it * 256;
                int r = gi >> 4, g = gi & 15;
                cp_async16(ka + (uint32_t)(r * 256 + (g >> 3) * 128 + (((g & 7) ^ (r & 7)) << 4)),
                           g_kb + base + (size_t)((kb + 1) * 64 + r) * CDIM + g * 8);
            }
            CP_COMMIT();
        }

        if (more) { CP_WAIT(2); } else { CP_WAIT(1); }
        __syncthreads();

        uint32_t Kc = (kb & 1) ? K1b : K0b;

        float s[8][4];
        #pragma unroll
        for (int nt = 0; nt < 8; nt++)
            #pragma unroll
            for (int r = 0; r < 4; r++) s[nt][r] = 0.f;

        #pragma unroll
        for (int kt = 0; kt < 8; kt++) {
            int ga = kt * 2 + lg;
            uint32_t a0, a1, a2, a3;
            LDMX4(a0, a1, a2, a3,
                  Qb + frow * 256 + (uint32_t)((ga >> 3) * 128 + (((ga & 7) ^ (frow & 7)) << 4)));
            int gb = kt * 2 + lh;
            #pragma unroll
            for (int nt = 0; nt < 8; nt++) {
                uint32_t krow = (uint32_t)(nt * 8 + l7);
                uint32_t b0, b1;
                LDMX2(b0, b1,
                      Kc + krow * 256 + (uint32_t)((gb >> 3) * 128 + (((gb & 7) ^ (krow & 7)) << 4)));
                MMA_BF16(s[nt], a0, a1, a2, a3, b0, b1);
            }
        }

        bool needmask = (kb * 64 + 63 > qb * 128 + warp * 16);
        float t0 = -1e30f, t1 = -1e30f;
        #pragma unroll
        for (int nt = 0; nt < 8; nt++) {
            if (needmask) {
                int cc0 = kb * 64 + nt * 8 + 2 * lr;
                s[nt][0] = (cc0     <= grow0)     ? s[nt][0] * scale : -1e30f;
                s[nt][1] = (cc0 + 1 <= grow0)     ? s[nt][1] * scale : -1e30f;
                s[nt][2] = (cc0     <= grow0 + 8) ? s[nt][2] * scale : -1e30f;
                s[nt][3] = (cc0 + 1 <= grow0 + 8) ? s[nt][3] * scale : -1e30f;
            } else {
                s[nt][0] *= scale; s[nt][1] *= scale;
                s[nt][2] *= scale; s[nt][3] *= scale;
            }
            t0 = fmaxf(t0, fmaxf(s[nt][0], s[nt][1]));
            t1 = fmaxf(t1, fmaxf(s[nt][2], s[nt][3]));
        }
        t0 = fmaxf(t0, __shfl_xor_sync(0xffffffffu, t0, 1));
        t0 = fmaxf(t0, __shfl_xor_sync(0xffffffffu, t0, 2));
        t1 = fmaxf(t1, __shfl_xor_sync(0xffffffffu, t1, 1));
        t1 = fmaxf(t1, __shfl_xor_sync(0xffffffffu, t1, 2));

        float mn0 = fmaxf(m0, t0), mn1 = fmaxf(m1, t1);
        float al0 = __expf(m0 - mn0), al1 = __expf(m1 - mn1);
        float rs0 = 0.f, rs1 = 0.f;
        int pr0 = srow, pr1 = srow + 8;
        #pragma unroll
        for (int nt = 0; nt < 8; nt++) {
            __nv_bfloat162 h0 = __floats2bfloat162_rn(__expf(s[nt][0] - mn0),
                                                      __expf(s[nt][1] - mn0));
            __nv_bfloat162 h1 = __floats2bfloat162_rn(__expf(s[nt][2] - mn1),
                                                      __expf(s[nt][3] - mn1));
            rs0 += __bfloat162float(h0.x) + __bfloat162float(h0.y);
            rs1 += __bfloat162float(h1.x) + __bfloat162float(h1.y);
            *(__nv_bfloat162*)(Pp + pr0 * 128 + ((nt ^ (pr0 & 7)) << 4) + 4 * lr) = h0;
            *(__nv_bfloat162*)(Pp + pr1 * 128 + ((nt ^ (pr1 & 7)) << 4) + 4 * lr) = h1;
        }
        rs0 += __shfl_xor_sync(0xffffffffu, rs0, 1);
        rs0 += __shfl_xor_sync(0xffffffffu, rs0, 2);
        rs1 += __shfl_xor_sync(0xffffffffu, rs1, 1);
        rs1 += __shfl_xor_sync(0xffffffffu, rs1, 2);

        l0 = l0 * al0 + rs0;  l1 = l1 * al1 + rs1;
        m0 = mn0;             m1 = mn1;
        #pragma unroll
        for (int nt = 0; nt < 16; nt++) {
            O[nt][0] *= al0; O[nt][1] *= al0;
            O[nt][2] *= al1; O[nt][3] *= al1;
        }
        __syncwarp();

        if (more) { CP_WAIT(1); } else { CP_WAIT(0); }
        __syncthreads();

        #pragma unroll
        for (int kt = 0; kt < 4; kt++) {
            int ga = kt * 2 + lg;
            uint32_t a0, a1, a2, a3;
            LDMX4(a0, a1, a2, a3,
                  Pb + frow * 128 + (uint32_t)(((ga ^ (frow & 7)) << 4)));
            uint32_t vrow = (uint32_t)(kt * 16 + lh * 8 + l7);
            uint32_t vbase = Vb + vrow * 256;
            uint32_t vsw = (vrow & 7) << 4;
            #pragma unroll
            for (int nt = 0; nt < 16; nt++) {
                uint32_t b0, b1;
                LDMX2T(b0, b1,
                       vbase + (uint32_t)((nt >> 3) * 128) + ((((uint32_t)(nt & 7) << 4) ^ vsw)));
                MMA_BF16(O[nt], a0, a1, a2, a3, b0, b1);
            }
        }
    }

    float inv0 = 1.f / l0, inv1 = 1.f / l1;
    size_t row0 = (size_t)b * TSEQ + grow0;
    #pragma unroll
    for (int nt = 0; nt < 16; nt++) {
        int col = h * HDIM + nt * 8 + 2 * lr;
        *(__nv_bfloat162*)(g_att + row0 * CDIM + col) =
            __floats2bfloat162_rn(O[nt][0] * inv0, O[nt][1] * inv0);
        *(__nv_bfloat162*)(g_att + (row0 + 8) * CDIM + col) =
            __floats2bfloat162_rn(O[nt][2] * inv1, O[nt][3] * inv1);
    }
}

// ===================== launch =====================
extern "C" void kernel_launch(void* const* d_in, const int* in_sizes, int n_in,
                              void* d_out, int out_size) {
    const float* x    = (const float*)d_in[0];
    const float* ln_g = (const float*)d_in[1];
    const float* ln_b = (const float*)d_in[2];
    const float* Wq   = (const float*)d_in[3];
    const float* bq   = (const float*)d_in[4];
    const float* Wk   = (const float*)d_in[5];
    const float* bk   = (const float*)d_in[6];
    const float* Wv   = (const float*)d_in[7];
    const float* bv   = (const float*)d_in[8];
    const float* Wo   = (const float*)d_in[9];
    const float* bo   = (const float*)d_in[10];
    float* out = (float*)d_out;

    __nv_bfloat16 *nx, *ap, *wq, *wk, *wv, *wo, *qb, *kb, *vb;
    cudaGetSymbolAddress((void**)&nx, g_nx);
    cudaGetSymbolAddress((void**)&qb, g_qb);
    cudaGetSymbolAddress((void**)&kb, g_kb);
    cudaGetSymbolAddress((void**)&vb, g_vb);
    cudaGetSymbolAddress((void**)&ap, g_att);
    cudaGetSymbolAddress((void**)&wq, g_wq);
    cudaGetSymbolAddress((void**)&wk, g_wk);
    cudaGetSymbolAddress((void**)&wv, g_wv);
    cudaGetSymbolAddress((void**)&wo, g_wo);

    cudaFuncSetAttribute(flash_bf_kernel, cudaFuncAttributeMaxDynamicSharedMemorySize, FLASHB_SMEM);
    cudaFuncSetAttribute(tg5_kernel<0>, cudaFuncAttributeMaxDynamicSharedMemorySize, TG5_SMEM);
    cudaFuncSetAttribute(tg5_kernel<1>, cudaFuncAttributeMaxDynamicSharedMemorySize, TG5_SMEM);

    // LN + weight transform + rope table, one launch
    prep_kernel<<<25600, 256>>>(x, ln_g, ln_b, Wq, Wk, Wv, Wo);

    // fused Q/K/V projections (bf16), rope fused in epilogue for q,k
    tg5_kernel<0><<<dim3(16, 64, 3), 256, TG5_SMEM>>>(
        nx, wq, wk, wv, bq, bk, bv, nullptr, nullptr, qb, kb, vb);

    flash_bf_kernel<<<dim3(TSEQ / 128, NHEAD, 4), 256, FLASHB_SMEM>>>();

    // output projection + residual (bf16 operands, fp32 out)
    tg5_kernel<1><<<dim3(16, 64, 1), 256, TG5_SMEM>>>(
        ap, wo, wo, wo, bo, bo, bo, x, out, nullptr, nullptr, nullptr);
}

// round 16
// speedup vs baseline: 2.4226x; 1.0293x over previous
#include <cuda_runtime.h>
#include <cuda_bf16.h>
#include <math.h>
#include <stdint.h>

#define BTOT 8192      // B*T rows
#define CDIM 2048      // channels
#define TSEQ 2048      // sequence length
#define NHEAD 16
#define HDIM 128

// -------- scratch (device globals; allocation-free) --------
__device__ __nv_bfloat16 g_nx [BTOT * CDIM];   // LN out, bf16
__device__ __nv_bfloat16 g_qb [BTOT * CDIM];   // q (rope applied), bf16
__device__ __nv_bfloat16 g_kb [BTOT * CDIM];   // k (rope applied), bf16
__device__ __nv_bfloat16 g_vb [BTOT * CDIM];   // v, bf16
__device__ __nv_bfloat16 g_att[BTOT * CDIM];   // flash out, bf16
__device__ __nv_bfloat16 g_wq [CDIM * CDIM];   // Wt[n][k], bf16
__device__ __nv_bfloat16 g_wk [CDIM * CDIM];
__device__ __nv_bfloat16 g_wv [CDIM * CDIM];
__device__ __nv_bfloat16 g_wo [CDIM * CDIM];
__device__ float g_rope[TSEQ * 128];           // row t: [0..63]=cos, [64..127]=sin

__device__ __forceinline__ void cp_async16(uint32_t dst_smem, const void* src) {
    asm volatile("cp.async.cg.shared.global [%0], [%1], 16;\n"
                 :: "r"(dst_smem), "l"(src));
}
#define CP_COMMIT() asm volatile("cp.async.commit_group;\n" ::: "memory")
#define CP_WAIT(n)  asm volatile("cp.async.wait_group %0;\n" :: "n"(n) : "memory")

#define LDMX4(r0, r1, r2, r3, addr) \
    asm volatile("ldmatrix.sync.aligned.m8n8.x4.shared.b16 {%0,%1,%2,%3}, [%4];" \
                 : "=r"(r0), "=r"(r1), "=r"(r2), "=r"(r3) : "r"(addr))
#define LDMX4T(r0, r1, r2, r3, addr) \
    asm volatile("ldmatrix.sync.aligned.m8n8.x4.trans.shared.b16 {%0,%1,%2,%3}, [%4];" \
                 : "=r"(r0), "=r"(r1), "=r"(r2), "=r"(r3) : "r"(addr))
#define MMA_BF16(c, a0, a1, a2, a3, b0, b1) \
    asm volatile("mma.sync.aligned.m16n8k16.row.col.f32.bf16.bf16.f32 " \
                 "{%0,%1,%2,%3}, {%4,%5,%6,%7}, {%8,%9}, {%0,%1,%2,%3};" \
                 : "+f"((c)[0]), "+f"((c)[1]), "+f"((c)[2]), "+f"((c)[3]) \
                 : "r"(a0), "r"(a1), "r"(a2), "r"(a3), "r"(b0), "r"(b1))

// ===================== Prep: LN + weight transform + rope table =====================
__global__ __launch_bounds__(256) void prep_kernel(
    const float* __restrict__ x,
    const float* __restrict__ gamma, const float* __restrict__ beta,
    const float* __restrict__ Wq, const float* __restrict__ Wk,
    const float* __restrict__ Wv, const float* __restrict__ Wo) {
    __shared__ float sh[16];
    __shared__ float tile[32][33];
    int bx = blockIdx.x, tid = threadIdx.x;

    if (bx < 8192) {                      // ---- LayerNorm ----
        const float* px = x + (size_t)bx * CDIM;
        float4 a0 = *(const float4*)(px + tid * 4);
        float4 a1 = *(const float4*)(px + 1024 + tid * 4);

        float s = a0.x + a0.y + a0.z + a0.w + a1.x + a1.y + a1.z + a1.w;
        float q = a0.x*a0.x + a0.y*a0.y + a0.z*a0.z + a0.w*a0.w
                + a1.x*a1.x + a1.y*a1.y + a1.z*a1.z + a1.w*a1.w;
        #pragma unroll
        for (int off = 16; off; off >>= 1) {
            s += __shfl_xor_sync(0xffffffffu, s, off);
            q += __shfl_xor_sync(0xffffffffu, q, off);
        }
        if ((tid & 31) == 0) { sh[tid >> 5] = s; sh[8 + (tid >> 5)] = q; }
        __syncthreads();
        float ts = 0.f, tq = 0.f;
        #pragma unroll
        for (int i = 0; i < 8; i++) { ts += sh[i]; tq += sh[8 + i]; }

        float mu   = ts * (1.f / 2048.f);
        float var  = tq * (1.f / 2048.f) - mu * mu;
        float rstd = rsqrtf(var + 1e-5f);

        float4 g0 = *(const float4*)(gamma + tid * 4);
        float4 g1 = *(const float4*)(gamma + 1024 + tid * 4);
        float4 b0 = *(const float4*)(beta + tid * 4);
        float4 b1 = *(const float4*)(beta + 1024 + tid * 4);

        __nv_bfloat16* po = g_nx + (size_t)bx * CDIM;
        float o[8];
        o[0] = (a0.x - mu) * rstd * g0.x + b0.x;
        o[1] = (a0.y - mu) * rstd * g0.y + b0.y;
        o[2] = (a0.z - mu) * rstd * g0.z + b0.z;
        o[3] = (a0.w - mu) * rstd * g0.w + b0.w;
        o[4] = (a1.x - mu) * rstd * g1.x + b1.x;
        o[5] = (a1.y - mu) * rstd * g1.y + b1.y;
        o[6] = (a1.z - mu) * rstd * g1.z + b1.z;
        o[7] = (a1.w - mu) * rstd * g1.w + b1.w;
        *(__nv_bfloat162*)(po + 4 * tid)            = __floats2bfloat162_rn(o[0], o[1]);
        *(__nv_bfloat162*)(po + 4 * tid + 2)        = __floats2bfloat162_rn(o[2], o[3]);
        *(__nv_bfloat162*)(po + 1024 + 4 * tid)     = __floats2bfloat162_rn(o[4], o[5]);
        *(__nv_bfloat162*)(po + 1024 + 4 * tid + 2) = __floats2bfloat162_rn(o[6], o[7]);
    } else if (bx < 24576) {              // ---- weight transform ----
        int idx = bx - 8192;
        int z = idx >> 12, rem = idx & 4095;
        int k0 = (rem >> 6) * 32, n0 = (rem & 63) * 32;
        const float* W = (z == 0) ? Wq : (z == 1) ? Wk : (z == 2) ? Wv : Wo;
        __nv_bfloat16* Wt = (z == 0) ? g_wq : (z == 1) ? g_wk : (z == 2) ? g_wv : g_wo;

        int c = tid & 31, r = tid >> 5;
        #pragma unroll
        for (int i = 0; i < 4; i++)
            tile[r + 8 * i][c] = W[(size_t)(k0 + r + 8 * i) * CDIM + n0 + c];
        __syncthreads();
        #pragma unroll
        for (int i = 0; i < 4; i++)
            Wt[(size_t)(n0 + r + 8 * i) * CDIM + k0 + c] =
                __float2bfloat16_rn(tile[c][r + 8 * i]);
    } else {                              // ---- rope table ----
        int t = (bx - 24576) * 2 + (tid >> 7);
        int c = tid & 127, f = c & 63;
        float inv = powf(10000.f, -(float)f / 64.f);
        float ang = (float)t * inv;
        g_rope[t * 128 + c] = (c < 64) ? cosf(ang) : sinf(ang);
    }
}

// ===================== bf16 GEMM v6.1: x4-batched B fragments =====================
#define TG5_SMEM (6 * 16384)

template<int MODE>   // 0: QKV (rope for z<2, bf16 out) ; 1: Wo (+bias+res, fp32)
__global__ __launch_bounds__(256, 2) void tg5_kernel(
    const __nv_bfloat16* __restrict__ A,
    const __nv_bfloat16* __restrict__ B0, const __nv_bfloat16* __restrict__ B1,
    const __nv_bfloat16* __restrict__ B2,
    const float* __restrict__ c0, const float* __restrict__ c1, const float* __restrict__ c2,
    const float* __restrict__ R,
    float* __restrict__ Yf,
    __nv_bfloat16* __restrict__ Yb0, __nv_bfloat16* __restrict__ Yb1,
    __nv_bfloat16* __restrict__ Yb2)
{
    const int N = CDIM;
    extern __shared__ char sm5[];
    uint32_t sb = (uint32_t)__cvta_generic_to_shared(sm5);

    int z = blockIdx.z;
    const __nv_bfloat16* Wt = (z == 0) ? B0 : (z == 1) ? B1 : B2;
    const float* bias = (z == 0) ? c0 : (z == 1) ? c1 : c2;

    int tid = threadIdx.x, lane = tid & 31, warp = tid >> 5;
    int bm = blockIdx.y * 128, bn = blockIdx.x * 128;

    int r = tid >> 3, cch = tid & 7;
    uint32_t swoff = (uint32_t)(r * 128 + ((cch ^ (r & 7)) << 4));
    const __nv_bfloat16* Ap = A  + (size_t)(bm + r) * CDIM + cch * 8;
    const __nv_bfloat16* Bp = Wt + (size_t)(bn + r) * CDIM + cch * 8;

    float c[4][4][4];
    #pragma unroll
    for (int mi = 0; mi < 4; mi++)
        #pragma unroll
        for (int ni = 0; ni < 4; ni++)
            #pragma unroll
            for (int q = 0; q < 4; q++) c[mi][ni][q] = 0.f;

    int wm = warp >> 2, wn = warp & 3;
    int mbase = wm * 64;
    int lq = lane >> 2, lr = lane & 3;
    int l7 = lane & 7, lh = (lane >> 3) & 1, lg = lane >> 4;

    // split-half column base per n-tile: {0,8,64,72} + wn*16
    int colof[4];
    #pragma unroll
    for (int ni = 0; ni < 4; ni++)
        colof[ni] = wn * 16 + (ni & 1) * 8 + (ni >> 1) * 64;

    auto issue = [&](int i, int s) {
        int k0 = i * 64;
        uint32_t da = sb + (uint32_t)s * 16384 + swoff;
        uint32_t db = sb + 49152u + (uint32_t)s * 16384 + swoff;
        #pragma unroll
        for (int it = 0; it < 4; it++) {
            cp_async16(da + it * 4096, Ap + (size_t)(it * 32) * CDIM + k0);
            cp_async16(db + it * 4096, Bp + (size_t)(it * 32) * CDIM + k0);
        }
        CP_COMMIT();
    };

    issue(0, 0);
    issue(1, 1);

    uint32_t arow = (uint32_t)(mbase + lh * 8 + l7);
    // x4 B row: lanes 16-31 (lg=1) fetch the pair's second n-tile (+8 rows)
    uint32_t brow_x4 = (uint32_t)(wn * 16 + lg * 8 + l7);

    const int NITER = CDIM / 64;   // 32
    for (int i = 0; i < NITER; ++i) {
        int s = i - (i / 3) * 3;
        if (i == NITER - 1) { CP_WAIT(0); } else { CP_WAIT(1); }
        __syncthreads();
        if (i + 2 < NITER) issue(i + 2, (i + 2) % 3);

        uint32_t Ab = sb + (uint32_t)s * 16384;
        uint32_t Bb = sb + 49152u + (uint32_t)s * 16384;

        #pragma unroll
        for (int kt = 0; kt < 4; kt++) {
            uint32_t b[4][2];
            uint32_t bch = (uint32_t)(((2 * kt + lh) ^ l7) << 4);
            // pair (ni, ni+1): m0/m1 = ni k-halves, m2/m3 = ni+1 k-halves
            #pragma unroll
            for (int np = 0; np < 2; np++)
                LDMX4(b[2 * np][0], b[2 * np][1], b[2 * np + 1][0], b[2 * np + 1][1],
                      Bb + (brow_x4 + (uint32_t)(np * 64)) * 128 + bch);
            uint32_t ach = (uint32_t)(((2 * kt + lg) ^ l7) << 4);
            #pragma unroll
            for (int mi = 0; mi < 4; mi++) {
                uint32_t a0, a1, a2, a3;
                LDMX4(a0, a1, a2, a3, Ab + (arow + mi * 16) * 128 + ach);
                #pragma unroll
                for (int ni = 0; ni < 4; ni++)
                    MMA_BF16(c[mi][ni], a0, a1, a2, a3, b[ni][0], b[ni][1]);
            }
        }
    }

    if (MODE == 0) {
        __nv_bfloat16* Yb = (z == 0) ? Yb0 : (z == 1) ? Yb1 : Yb2;
        #pragma unroll
        for (int mi = 0; mi < 4; mi++) {
            int r0 = bm + mbase + mi * 16 + lq;
            if (z < 2) {
                int t0 = r0 & (TSEQ - 1), t1 = (r0 + 8) & (TSEQ - 1);
                #pragma unroll
                for (int p = 0; p < 2; p++) {
                    int f = colof[p] + 2 * lr;
                    float bx  = bias[bn + f],      by  = bias[bn + f + 1];
                    float bx2 = bias[bn + f + 64], by2 = bias[bn + f + 65];
                    float2 cs0 = *(const float2*)&g_rope[t0 * 128 + f];
                    float2 sn0 = *(const float2*)&g_rope[t0 * 128 + 64 + f];
                    float2 cs1 = *(const float2*)&g_rope[t1 * 128 + f];
                    float2 sn1 = *(const float2*)&g_rope[t1 * 128 + 64 + f];
                    float a0 = c[mi][p][0] + bx,      a1 = c[mi][p][1] + by;
                    float q0 = c[mi][p + 2][0] + bx2, q1 = c[mi][p + 2][1] + by2;
                    *(__nv_bfloat162*)(Yb + (size_t)r0 * N + bn + f) =
                        __floats2bfloat162_rn(a0 * cs0.x - q0 * sn0.x,
                                              a1 * cs0.y - q1 * sn0.y);
                    *(__nv_bfloat162*)(Yb + (size_t)r0 * N + bn + f + 64) =
                        __floats2bfloat162_rn(q0 * cs0.x + a0 * sn0.x,
                                              q1 * cs0.y + a1 * sn0.y);
                    float a2 = c[mi][p][2] + bx,      a3 = c[mi][p][3] + by;
                    float q2 = c[mi][p + 2][2] + bx2, q3 = c[mi][p + 2][3] + by2;
                    *(__nv_bfloat162*)(Yb + (size_t)(r0 + 8) * N + bn + f) =
                        __floats2bfloat162_rn(a2 * cs1.x - q2 * sn1.x,
                                              a3 * cs1.y - q3 * sn1.y);
                    *(__nv_bfloat162*)(Yb + (size_t)(r0 + 8) * N + bn + f + 64) =
                        __floats2bfloat162_rn(q2 * cs1.x + a2 * sn1.x,
                                              q3 * cs1.y + a3 * sn1.y);
                }
            } else {
                #pragma unroll
                for (int ni = 0; ni < 4; ni++) {
                    int cb = bn + colof[ni] + 2 * lr;
                    float bx = bias[cb], by = bias[cb + 1];
                    *(__nv_bfloat162*)(Yb + (size_t)r0 * N + cb) =
                        __floats2bfloat162_rn(c[mi][ni][0] + bx, c[mi][ni][1] + by);
                    *(__nv_bfloat162*)(Yb + (size_t)(r0 + 8) * N + cb) =
                        __floats2bfloat162_rn(c[mi][ni][2] + bx, c[mi][ni][3] + by);
                }
            }
        }
    } else {
        #pragma unroll
        for (int mi = 0; mi < 4; mi++) {
            int r0 = bm + mbase + mi * 16 + lq;
            #pragma unroll
            for (int ni = 0; ni < 4; ni++) {
                int cb = bn + colof[ni] + 2 * lr;
                float bx = bias[cb], by = bias[cb + 1];
                float2 v0 = make_float2(c[mi][ni][0] + bx, c[mi][ni][1] + by);
                float2 v1 = make_float2(c[mi][ni][2] + bx, c[mi][ni][3] + by);
                float2 r0v = *(const float2*)(R + (size_t)r0 * N + cb);
                float2 r1v = *(const float2*)(R + (size_t)(r0 + 8) * N + cb);
                v0.x += r0v.x; v0.y += r0v.y;
                v1.x += r1v.x; v1.y += r1v.y;
                *(float2*)(Yf + (size_t)r0 * N + cb)       = v0;
                *(float2*)(Yf + (size_t)(r0 + 8) * N + cb) = v1;
            }
        }
    }
}

// ===================== Flash attention v4.1: x4-batched K and V fragments =========
#define FLASHB_SMEM 98304

__global__ __launch_bounds__(256, 1) void flash_bf_kernel() {
    extern __shared__ char smf[];
    uint32_t sb = (uint32_t)__cvta_generic_to_shared(smf);
    uint32_t Qb = sb, K0b = sb + 32768u, K1b = sb + 49152u;
    uint32_t Vb = sb + 65536u, Pb = sb + 81920u;
    char* Pp = smf + 81920;

    int qb = gridDim.x - 1 - blockIdx.x;
    int h = blockIdx.y, b = blockIdx.z;
    int tid = threadIdx.x, lane = tid & 31, warp = tid >> 5;
    int lq = lane >> 2, lr = lane & 3;
    int l7 = lane & 7, lh = (lane >> 3) & 1, lg = lane >> 4;

    size_t base = ((size_t)b * TSEQ) * CDIM + (size_t)h * HDIM;

    #pragma unroll
    for (int it = 0; it < 8; it++) {
        int gi = tid + it * 256;
        int r = gi >> 4, g = gi & 15;
        cp_async16(Qb + (uint32_t)(r * 256 + (g >> 3) * 128 + (((g & 7) ^ (r & 7)) << 4)),
                   g_qb + base + (size_t)(qb * 128 + r) * CDIM + g * 8);
    }
    CP_COMMIT();

    #pragma unroll
    for (int it = 0; it < 4; it++) {
        int gi = tid + it * 256;
        int r = gi >> 4, g = gi & 15;
        cp_async16(K0b + (uint32_t)(r * 256 + (g >> 3) * 128 + (((g & 7) ^ (r & 7)) << 4)),
                   g_kb + base + (size_t)r * CDIM + g * 8);
    }
    CP_COMMIT();

    float m0 = -1e30f, m1 = -1e30f, l0 = 0.f, l1 = 0.f;
    float O[16][4];
    #pragma unroll
    for (int nt = 0; nt < 16; nt++)
        #pragma unroll
        for (int r = 0; r < 4; r++) O[nt][r] = 0.f;

    const float scale = 0.08838834764831845f;
    int srow = warp * 16 + lq;
    int grow0 = qb * 128 + srow;
    uint32_t frow = (uint32_t)(warp * 16 + lh * 8 + l7);
    int nkb = 2 * (qb + 1);

    for (int kb = 0; kb < nkb; kb++) {
        __syncthreads();

        #pragma unroll
        for (int it = 0; it < 4; it++) {
            int gi = tid + it * 256;
            int r = gi >> 4, g = gi & 15;
            cp_async16(Vb + (uint32_t)(r * 256 + (g >> 3) * 128 + (((g & 7) ^ (r & 7)) << 4)),
                       g_vb + base + (size_t)(kb * 64 + r) * CDIM + g * 8);
        }
        CP_COMMIT();

        bool more = (kb + 1 < nkb);
        if (more) {
            uint32_t ka = ((kb + 1) & 1) ? K1b : K0b;
            #pragma unroll
            for (int it = 0; it < 4; it++) {
                int gi = tid + it * 256;
                int r = gi >> 4, g = gi & 15;
                cp_async16(ka + (uint32_t)(r * 256 + (g >> 3) * 128 + (((g & 7) ^ (r & 7)) << 4)),
                           g_kb + base + (size_t)((kb + 1) * 64 + r) * CDIM + g * 8);
            }
            CP_COMMIT();
        }

        if (more) { CP_WAIT(2); } else { CP_WAIT(1); }
        __syncthreads();

        uint32_t Kc = (kb & 1) ? K1b : K0b;

        // ---- S = Q K^T : K fragments via x4 (nt pairs) ----
        float s[8][4];
        #pragma unroll
        for (int nt = 0; nt < 8; nt++)
            #pragma unroll
            for (int r = 0; r < 4; r++) s[nt][r] = 0.f;

        #pragma unroll
        for (int kt = 0; kt < 8; kt++) {
            int ga = kt * 2 + lg;
            uint32_t a0, a1, a2, a3;
            LDMX4(a0, a1, a2, a3,
                  Qb + frow * 256 + (uint32_t)((ga >> 3) * 128 + (((ga & 7) ^ (frow & 7)) << 4)));
            int gb = kt * 2 + lh;
            uint32_t gbo = (uint32_t)((gb >> 3) * 128 + (((gb & 7) ^ l7) << 4));
            #pragma unroll
            for (int np = 0; np < 4; np++) {
                // m0/m1 = nt=2np k-halves, m2/m3 = nt=2np+1 (lanes 16-31)
                uint32_t krow = (uint32_t)((np * 2 + lg) * 8 + l7);
                uint32_t b0, b1, b2, b3;
                LDMX4(b0, b1, b2, b3, Kc + krow * 256 + gbo);
                MMA_BF16(s[2 * np],     a0, a1, a2, a3, b0, b1);
                MMA_BF16(s[2 * np + 1], a0, a1, a2, a3, b2, b3);
            }
        }

        bool needmask = (kb * 64 + 63 > qb * 128 + warp * 16);
        float t0 = -1e30f, t1 = -1e30f;
        #pragma unroll
        for (int nt = 0; nt < 8; nt++) {
            if (needmask) {
                int cc0 = kb * 64 + nt * 8 + 2 * lr;
                s[nt][0] = (cc0     <= grow0)     ? s[nt][0] * scale : -1e30f;
                s[nt][1] = (cc0 + 1 <= grow0)     ? s[nt][1] * scale : -1e30f;
                s[nt][2] = (cc0     <= grow0 + 8) ? s[nt][2] * scale : -1e30f;
                s[nt][3] = (cc0 + 1 <= grow0 + 8) ? s[nt][3] * scale : -1e30f;
            } else {
                s[nt][0] *= scale; s[nt][1] *= scale;
                s[nt][2] *= scale; s[nt][3] *= scale;
            }
            t0 = fmaxf(t0, fmaxf(s[nt][0], s[nt][1]));
            t1 = fmaxf(t1, fmaxf(s[nt][2], s[nt][3]));
        }
        t0 = fmaxf(t0, __shfl_xor_sync(0xffffffffu, t0, 1));
        t0 = fmaxf(t0, __shfl_xor_sync(0xffffffffu, t0, 2));
        t1 = fmaxf(t1, __shfl_xor_sync(0xffffffffu, t1, 1));
        t1 = fmaxf(t1, __shfl_xor_sync(0xffffffffu, t1, 2));

        float mn0 = fmaxf(m0, t0), mn1 = fmaxf(m1, t1);
        float al0 = __expf(m0 - mn0), al1 = __expf(m1 - mn1);
        float rs0 = 0.f, rs1 = 0.f;
        int pr0 = srow, pr1 = srow + 8;
        #pragma unroll
        for (int nt = 0; nt < 8; nt++) {
            __nv_bfloat162 h0 = __floats2bfloat162_rn(__expf(s[nt][0] - mn0),
                                                      __expf(s[nt][1] - mn0));
            __nv_bfloat162 h1 = __floats2bfloat162_rn(__expf(s[nt][2] - mn1),
                                                      __expf(s[nt][3] - mn1));
            rs0 += __bfloat162float(h0.x) + __bfloat162float(h0.y);
            rs1 += __bfloat162float(h1.x) + __bfloat162float(h1.y);
            *(__nv_bfloat162*)(Pp + pr0 * 128 + ((nt ^ (pr0 & 7)) << 4) + 4 * lr) = h0;
            *(__nv_bfloat162*)(Pp + pr1 * 128 + ((nt ^ (pr1 & 7)) << 4) + 4 * lr) = h1;
        }
        rs0 += __shfl_xor_sync(0xffffffffu, rs0, 1);
        rs0 += __shfl_xor_sync(0xffffffffu, rs0, 2);
        rs1 += __shfl_xor_sync(0xffffffffu, rs1, 1);
        rs1 += __shfl_xor_sync(0xffffffffu, rs1, 2);

        l0 = l0 * al0 + rs0;  l1 = l1 * al1 + rs1;
        m0 = mn0;             m1 = mn1;
        #pragma unroll
        for (int nt = 0; nt < 16; nt++) {
            O[nt][0] *= al0; O[nt][1] *= al0;
            O[nt][2] *= al1; O[nt][3] *= al1;
        }
        __syncwarp();

        if (more) { CP_WAIT(1); } else { CP_WAIT(0); }
        __syncthreads();

        // ---- O += P V : V fragments via x4.trans (col-block pairs) ----
        #pragma unroll
        for (int kt = 0; kt < 4; kt++) {
            int ga = kt * 2 + lg;
            uint32_t a0, a1, a2, a3;
            LDMX4(a0, a1, a2, a3,
                  Pb + frow * 128 + (uint32_t)(((ga ^ (frow & 7)) << 4)));
            uint32_t vrow = (uint32_t)(kt * 16 + lh * 8 + l7);   // lh: row-half
            uint32_t vbase = Vb + vrow * 256;
            uint32_t vsw = (vrow & 7) << 4;
            #pragma unroll
            for (int np = 0; np < 8; np++) {
                int cblk = np * 2 + lg;   // lg: col-block within pair
                uint32_t b0, b1, b2, b3;
                LDMX4T(b0, b1, b2, b3,
                       vbase + (uint32_t)((cblk >> 3) * 128) +
                       ((((uint32_t)(cblk & 7) << 4) ^ vsw)));
                MMA_BF16(O[2 * np],     a0, a1, a2, a3, b0, b1);
                MMA_BF16(O[2 * np + 1], a0, a1, a2, a3, b2, b3);
            }
        }
    }

    float inv0 = 1.f / l0, inv1 = 1.f / l1;
    size_t row0 = (size_t)b * TSEQ + grow0;
    #pragma unroll
    for (int nt = 0; nt < 16; nt++) {
        int col = h * HDIM + nt * 8 + 2 * lr;
        *(__nv_bfloat162*)(g_att + row0 * CDIM + col) =
            __floats2bfloat162_rn(O[nt][0] * inv0, O[nt][1] * inv0);
        *(__nv_bfloat162*)(g_att + (row0 + 8) * CDIM + col) =
            __floats2bfloat162_rn(O[nt][2] * inv1, O[nt][3] * inv1);
    }
}

// ===================== launch =====================
extern "C" void kernel_launch(void* const* d_in, const int* in_sizes, int n_in,
                              void* d_out, int out_size) {
    const float* x    = (const float*)d_in[0];
    const float* ln_g = (const float*)d_in[1];
    const float* ln_b = (const float*)d_in[2];
    const float* Wq   = (const float*)d_in[3];
    const float* bq   = (const float*)d_in[4];
    const float* Wk   = (const float*)d_in[5];
    const float* bk   = (const float*)d_in[6];
    const float* Wv   = (const float*)d_in[7];
    const float* bv   = (const float*)d_in[8];
    const float* Wo   = (const float*)d_in[9];
    const float* bo   = (const float*)d_in[10];
    float* out = (float*)d_out;

    __nv_bfloat16 *nx, *ap, *wq, *wk, *wv, *wo, *qb, *kb, *vb;
    cudaGetSymbolAddress((void**)&nx, g_nx);
    cudaGetSymbolAddress((void**)&qb, g_qb);
    cudaGetSymbolAddress((void**)&kb, g_kb);
    cudaGetSymbolAddress((void**)&vb, g_vb);
    cudaGetSymbolAddress((void**)&ap, g_att);
    cudaGetSymbolAddress((void**)&wq, g_wq);
    cudaGetSymbolAddress((void**)&wk, g_wk);
    cudaGetSymbolAddress((void**)&wv, g_wv);
    cudaGetSymbolAddress((void**)&wo, g_wo);

    cudaFuncSetAttribute(flash_bf_kernel, cudaFuncAttributeMaxDynamicSharedMemorySize, FLASHB_SMEM);
    cudaFuncSetAttribute(tg5_kernel<0>, cudaFuncAttributeMaxDynamicSharedMemorySize, TG5_SMEM);
    cudaFuncSetAttribute(tg5_kernel<1>, cudaFuncAttributeMaxDynamicSharedMemorySize, TG5_SMEM);

    prep_kernel<<<25600, 256>>>(x, ln_g, ln_b, Wq, Wk, Wv, Wo);

    tg5_kernel<0><<<dim3(16, 64, 3), 256, TG5_SMEM>>>(
        nx, wq, wk, wv, bq, bk, bv, nullptr, nullptr, qb, kb, vb);

    flash_bf_kernel<<<dim3(TSEQ / 128, NHEAD, 4), 256, FLASHB_SMEM>>>();

    tg5_kernel<1><<<dim3(16, 64, 1), 256, TG5_SMEM>>>(
        ap, wo, wo, wo, bo, bo, bo, x, out, nullptr, nullptr, nullptr);
}

// round 17
// speedup vs baseline: 2.4534x; 1.0127x over previous
#include <cuda_runtime.h>
#include <cuda_bf16.h>
#include <math.h>
#include <stdint.h>

#define BTOT 8192      // B*T rows
#define CDIM 2048      // channels
#define TSEQ 2048      // sequence length
#define NHEAD 16
#define HDIM 128

// -------- scratch (device globals; allocation-free) --------
__device__ __nv_bfloat16 g_nx [BTOT * CDIM];   // LN out, bf16
__device__ __nv_bfloat16 g_qb [BTOT * CDIM];   // q (rope applied), bf16
__device__ __nv_bfloat16 g_kb [BTOT * CDIM];   // k (rope applied), bf16
__device__ __nv_bfloat16 g_vb [BTOT * CDIM];   // v, bf16
__device__ __nv_bfloat16 g_att[BTOT * CDIM];   // flash out, bf16
__device__ __nv_bfloat16 g_wq [CDIM * CDIM];   // Wt[n][k], bf16
__device__ __nv_bfloat16 g_wk [CDIM * CDIM];
__device__ __nv_bfloat16 g_wv [CDIM * CDIM];
__device__ __nv_bfloat16 g_wo [CDIM * CDIM];
__device__ float g_rope[TSEQ * 128];           // row t: [0..63]=cos, [64..127]=sin

__device__ __forceinline__ void cp_async16(uint32_t dst_smem, const void* src) {
    asm volatile("cp.async.cg.shared.global [%0], [%1], 16;\n"
                 :: "r"(dst_smem), "l"(src));
}
#define CP_COMMIT() asm volatile("cp.async.commit_group;\n" ::: "memory")
#define CP_WAIT(n)  asm volatile("cp.async.wait_group %0;\n" :: "n"(n) : "memory")

#define LDMX4(r0, r1, r2, r3, addr) \
    asm volatile("ldmatrix.sync.aligned.m8n8.x4.shared.b16 {%0,%1,%2,%3}, [%4];" \
                 : "=r"(r0), "=r"(r1), "=r"(r2), "=r"(r3) : "r"(addr))
#define LDMX4T(r0, r1, r2, r3, addr) \
    asm volatile("ldmatrix.sync.aligned.m8n8.x4.trans.shared.b16 {%0,%1,%2,%3}, [%4];" \
                 : "=r"(r0), "=r"(r1), "=r"(r2), "=r"(r3) : "r"(addr))
#define MMA_BF16(c, a0, a1, a2, a3, b0, b1) \
    asm volatile("mma.sync.aligned.m16n8k16.row.col.f32.bf16.bf16.f32 " \
                 "{%0,%1,%2,%3}, {%4,%5,%6,%7}, {%8,%9}, {%0,%1,%2,%3};" \
                 : "+f"((c)[0]), "+f"((c)[1]), "+f"((c)[2]), "+f"((c)[3]) \
                 : "r"(a0), "r"(a1), "r"(a2), "r"(a3), "r"(b0), "r"(b1))

// ===================== Prep: LN + weight transform + rope table =====================
__global__ __launch_bounds__(256) void prep_kernel(
    const float* __restrict__ x,
    const float* __restrict__ gamma, const float* __restrict__ beta,
    const float* __restrict__ Wq, const float* __restrict__ Wk,
    const float* __restrict__ Wv, const float* __restrict__ Wo) {
    __shared__ float sh[16];
    __shared__ float tile[32][33];
    int bx = blockIdx.x, tid = threadIdx.x;

    if (bx < 8192) {                      // ---- LayerNorm ----
        const float* px = x + (size_t)bx * CDIM;
        float4 a0 = *(const float4*)(px + tid * 4);
        float4 a1 = *(const float4*)(px + 1024 + tid * 4);

        float s = a0.x + a0.y + a0.z + a0.w + a1.x + a1.y + a1.z + a1.w;
        float q = a0.x*a0.x + a0.y*a0.y + a0.z*a0.z + a0.w*a0.w
                + a1.x*a1.x + a1.y*a1.y + a1.z*a1.z + a1.w*a1.w;
        #pragma unroll
        for (int off = 16; off; off >>= 1) {
            s += __shfl_xor_sync(0xffffffffu, s, off);
            q += __shfl_xor_sync(0xffffffffu, q, off);
        }
        if ((tid & 31) == 0) { sh[tid >> 5] = s; sh[8 + (tid >> 5)] = q; }
        __syncthreads();
        float ts = 0.f, tq = 0.f;
        #pragma unroll
        for (int i = 0; i < 8; i++) { ts += sh[i]; tq += sh[8 + i]; }

        float mu   = ts * (1.f / 2048.f);
        float var  = tq * (1.f / 2048.f) - mu * mu;
        float rstd = rsqrtf(var + 1e-5f);

        float4 g0 = *(const float4*)(gamma + tid * 4);
        float4 g1 = *(const float4*)(gamma + 1024 + tid * 4);
        float4 b0 = *(const float4*)(beta + tid * 4);
        float4 b1 = *(const float4*)(beta + 1024 + tid * 4);

        __nv_bfloat16* po = g_nx + (size_t)bx * CDIM;
        float o[8];
        o[0] = (a0.x - mu) * rstd * g0.x + b0.x;
        o[1] = (a0.y - mu) * rstd * g0.y + b0.y;
        o[2] = (a0.z - mu) * rstd * g0.z + b0.z;
        o[3] = (a0.w - mu) * rstd * g0.w + b0.w;
        o[4] = (a1.x - mu) * rstd * g1.x + b1.x;
        o[5] = (a1.y - mu) * rstd * g1.y + b1.y;
        o[6] = (a1.z - mu) * rstd * g1.z + b1.z;
        o[7] = (a1.w - mu) * rstd * g1.w + b1.w;
        *(__nv_bfloat162*)(po + 4 * tid)            = __floats2bfloat162_rn(o[0], o[1]);
        *(__nv_bfloat162*)(po + 4 * tid + 2)        = __floats2bfloat162_rn(o[2], o[3]);
        *(__nv_bfloat162*)(po + 1024 + 4 * tid)     = __floats2bfloat162_rn(o[4], o[5]);
        *(__nv_bfloat162*)(po + 1024 + 4 * tid + 2) = __floats2bfloat162_rn(o[6], o[7]);
    } else if (bx < 24576) {              // ---- weight transform ----
        int idx = bx - 8192;
        int z = idx >> 12, rem = idx & 4095;
        int k0 = (rem >> 6) * 32, n0 = (rem & 63) * 32;
        const float* W = (z == 0) ? Wq : (z == 1) ? Wk : (z == 2) ? Wv : Wo;
        __nv_bfloat16* Wt = (z == 0) ? g_wq : (z == 1) ? g_wk : (z == 2) ? g_wv : g_wo;

        int c = tid & 31, r = tid >> 5;
        #pragma unroll
        for (int i = 0; i < 4; i++)
            tile[r + 8 * i][c] = W[(size_t)(k0 + r + 8 * i) * CDIM + n0 + c];
        __syncthreads();
        #pragma unroll
        for (int i = 0; i < 4; i++)
            Wt[(size_t)(n0 + r + 8 * i) * CDIM + k0 + c] =
                __float2bfloat16_rn(tile[c][r + 8 * i]);
    } else {                              // ---- rope table ----
        int t = (bx - 24576) * 2 + (tid >> 7);
        int c = tid & 127, f = c & 63;
        float inv = powf(10000.f, -(float)f / 64.f);
        float ang = (float)t * inv;
        g_rope[t * 128 + c] = (c < 64) ? cosf(ang) : sinf(ang);
    }
}

// ===================== bf16 GEMM v6.1: x4-batched B fragments =====================
#define TG5_SMEM (6 * 16384)

template<int MODE>   // 0: QKV (rope for z<2, bf16 out) ; 1: Wo (+bias+res, fp32)
__global__ __launch_bounds__(256, 2) void tg5_kernel(
    const __nv_bfloat16* __restrict__ A,
    const __nv_bfloat16* __restrict__ B0, const __nv_bfloat16* __restrict__ B1,
    const __nv_bfloat16* __restrict__ B2,
    const float* __restrict__ c0, const float* __restrict__ c1, const float* __restrict__ c2,
    const float* __restrict__ R,
    float* __restrict__ Yf,
    __nv_bfloat16* __restrict__ Yb0, __nv_bfloat16* __restrict__ Yb1,
    __nv_bfloat16* __restrict__ Yb2)
{
    const int N = CDIM;
    extern __shared__ char sm5[];
    uint32_t sb = (uint32_t)__cvta_generic_to_shared(sm5);

    int z = blockIdx.z;
    const __nv_bfloat16* Wt = (z == 0) ? B0 : (z == 1) ? B1 : B2;
    const float* bias = (z == 0) ? c0 : (z == 1) ? c1 : c2;

    int tid = threadIdx.x, lane = tid & 31, warp = tid >> 5;
    int bm = blockIdx.y * 128, bn = blockIdx.x * 128;

    int r = tid >> 3, cch = tid & 7;
    uint32_t swoff = (uint32_t)(r * 128 + ((cch ^ (r & 7)) << 4));
    const __nv_bfloat16* Ap = A  + (size_t)(bm + r) * CDIM + cch * 8;
    const __nv_bfloat16* Bp = Wt + (size_t)(bn + r) * CDIM + cch * 8;

    float c[4][4][4];
    #pragma unroll
    for (int mi = 0; mi < 4; mi++)
        #pragma unroll
        for (int ni = 0; ni < 4; ni++)
            #pragma unroll
            for (int q = 0; q < 4; q++) c[mi][ni][q] = 0.f;

    int wm = warp >> 2, wn = warp & 3;
    int mbase = wm * 64;
    int lq = lane >> 2, lr = lane & 3;
    int l7 = lane & 7, lh = (lane >> 3) & 1, lg = lane >> 4;

    int colof[4];
    #pragma unroll
    for (int ni = 0; ni < 4; ni++)
        colof[ni] = wn * 16 + (ni & 1) * 8 + (ni >> 1) * 64;

    auto issue = [&](int i, int s) {
        int k0 = i * 64;
        uint32_t da = sb + (uint32_t)s * 16384 + swoff;
        uint32_t db = sb + 49152u + (uint32_t)s * 16384 + swoff;
        #pragma unroll
        for (int it = 0; it < 4; it++) {
            cp_async16(da + it * 4096, Ap + (size_t)(it * 32) * CDIM + k0);
            cp_async16(db + it * 4096, Bp + (size_t)(it * 32) * CDIM + k0);
        }
        CP_COMMIT();
    };

    issue(0, 0);
    issue(1, 1);

    uint32_t arow = (uint32_t)(mbase + lh * 8 + l7);
    uint32_t brow_x4 = (uint32_t)(wn * 16 + lg * 8 + l7);

    const int NITER = CDIM / 64;   // 32
    for (int i = 0; i < NITER; ++i) {
        int s = i - (i / 3) * 3;
        if (i == NITER - 1) { CP_WAIT(0); } else { CP_WAIT(1); }
        __syncthreads();
        if (i + 2 < NITER) issue(i + 2, (i + 2) % 3);

        uint32_t Ab = sb + (uint32_t)s * 16384;
        uint32_t Bb = sb + 49152u + (uint32_t)s * 16384;

        #pragma unroll
        for (int kt = 0; kt < 4; kt++) {
            uint32_t b[4][2];
            uint32_t bch = (uint32_t)(((2 * kt + lh) ^ l7) << 4);
            #pragma unroll
            for (int np = 0; np < 2; np++)
                LDMX4(b[2 * np][0], b[2 * np][1], b[2 * np + 1][0], b[2 * np + 1][1],
                      Bb + (brow_x4 + (uint32_t)(np * 64)) * 128 + bch);
            uint32_t ach = (uint32_t)(((2 * kt + lg) ^ l7) << 4);
            #pragma unroll
            for (int mi = 0; mi < 4; mi++) {
                uint32_t a0, a1, a2, a3;
                LDMX4(a0, a1, a2, a3, Ab + (arow + mi * 16) * 128 + ach);
                #pragma unroll
                for (int ni = 0; ni < 4; ni++)
                    MMA_BF16(c[mi][ni], a0, a1, a2, a3, b[ni][0], b[ni][1]);
            }
        }
    }

    if (MODE == 0) {
        __nv_bfloat16* Yb = (z == 0) ? Yb0 : (z == 1) ? Yb1 : Yb2;
        #pragma unroll
        for (int mi = 0; mi < 4; mi++) {
            int r0 = bm + mbase + mi * 16 + lq;
            if (z < 2) {
                int t0 = r0 & (TSEQ - 1), t1 = (r0 + 8) & (TSEQ - 1);
                #pragma unroll
                for (int p = 0; p < 2; p++) {
                    int f = colof[p] + 2 * lr;
                    float bx  = bias[bn + f],      by  = bias[bn + f + 1];
                    float bx2 = bias[bn + f + 64], by2 = bias[bn + f + 65];
                    float2 cs0 = *(const float2*)&g_rope[t0 * 128 + f];
                    float2 sn0 = *(const float2*)&g_rope[t0 * 128 + 64 + f];
                    float2 cs1 = *(const float2*)&g_rope[t1 * 128 + f];
                    float2 sn1 = *(const float2*)&g_rope[t1 * 128 + 64 + f];
                    float a0 = c[mi][p][0] + bx,      a1 = c[mi][p][1] + by;
                    float q0 = c[mi][p + 2][0] + bx2, q1 = c[mi][p + 2][1] + by2;
                    *(__nv_bfloat162*)(Yb + (size_t)r0 * N + bn + f) =
                        __floats2bfloat162_rn(a0 * cs0.x - q0 * sn0.x,
                                              a1 * cs0.y - q1 * sn0.y);
                    *(__nv_bfloat162*)(Yb + (size_t)r0 * N + bn + f + 64) =
                        __floats2bfloat162_rn(q0 * cs0.x + a0 * sn0.x,
                                              q1 * cs0.y + a1 * sn0.y);
                    float a2 = c[mi][p][2] + bx,      a3 = c[mi][p][3] + by;
                    float q2 = c[mi][p + 2][2] + bx2, q3 = c[mi][p + 2][3] + by2;
                    *(__nv_bfloat162*)(Yb + (size_t)(r0 + 8) * N + bn + f) =
                        __floats2bfloat162_rn(a2 * cs1.x - q2 * sn1.x,
                                              a3 * cs1.y - q3 * sn1.y);
                    *(__nv_bfloat162*)(Yb + (size_t)(r0 + 8) * N + bn + f + 64) =
                        __floats2bfloat162_rn(q2 * cs1.x + a2 * sn1.x,
                                              q3 * cs1.y + a3 * sn1.y);
                }
            } else {
                #pragma unroll
                for (int ni = 0; ni < 4; ni++) {
                    int cb = bn + colof[ni] + 2 * lr;
                    float bx = bias[cb], by = bias[cb + 1];
                    *(__nv_bfloat162*)(Yb + (size_t)r0 * N + cb) =
                        __floats2bfloat162_rn(c[mi][ni][0] + bx, c[mi][ni][1] + by);
                    *(__nv_bfloat162*)(Yb + (size_t)(r0 + 8) * N + cb) =
                        __floats2bfloat162_rn(c[mi][ni][2] + bx, c[mi][ni][3] + by);
                }
            }
        }
    } else {
        #pragma unroll
        for (int mi = 0; mi < 4; mi++) {
            int r0 = bm + mbase + mi * 16 + lq;
            #pragma unroll
            for (int ni = 0; ni < 4; ni++) {
                int cb = bn + colof[ni] + 2 * lr;
                float bx = bias[cb], by = bias[cb + 1];
                float2 v0 = make_float2(c[mi][ni][0] + bx, c[mi][ni][1] + by);
                float2 v1 = make_float2(c[mi][ni][2] + bx, c[mi][ni][3] + by);
                float2 r0v = *(const float2*)(R + (size_t)r0 * N + cb);
                float2 r1v = *(const float2*)(R + (size_t)(r0 + 8) * N + cb);
                v0.x += r0v.x; v0.y += r0v.y;
                v1.x += r1v.x; v1.y += r1v.y;
                *(float2*)(Yf + (size_t)r0 * N + cb)       = v0;
                *(float2*)(Yf + (size_t)(r0 + 8) * N + cb) = v1;
            }
        }
    }
}

// ===================== Flash attention v4.2: 2 CTAs/SM =====================
#define FLASHB_SMEM 98304

__global__ __launch_bounds__(256, 2) void flash_bf_kernel() {
    extern __shared__ char smf[];
    uint32_t sb = (uint32_t)__cvta_generic_to_shared(smf);
    uint32_t Qb = sb, K0b = sb + 32768u, K1b = sb + 49152u;
    uint32_t Vb = sb + 65536u, Pb = sb + 81920u;
    char* Pp = smf + 81920;

    int qb = gridDim.x - 1 - blockIdx.x;
    int h = blockIdx.y, b = blockIdx.z;
    int tid = threadIdx.x, lane = tid & 31, warp = tid >> 5;
    int lq = lane >> 2, lr = lane & 3;
    int l7 = lane & 7, lh = (lane >> 3) & 1, lg = lane >> 4;

    size_t base = ((size_t)b * TSEQ) * CDIM + (size_t)h * HDIM;

    #pragma unroll
    for (int it = 0; it < 8; it++) {
        int gi = tid + it * 256;
        int r = gi >> 4, g = gi & 15;
        cp_async16(Qb + (uint32_t)(r * 256 + (g >> 3) * 128 + (((g & 7) ^ (r & 7)) << 4)),
                   g_qb + base + (size_t)(qb * 128 + r) * CDIM + g * 8);
    }
    CP_COMMIT();

    #pragma unroll
    for (int it = 0; it < 4; it++) {
        int gi = tid + it * 256;
        int r = gi >> 4, g = gi & 15;
        cp_async16(K0b + (uint32_t)(r * 256 + (g >> 3) * 128 + (((g & 7) ^ (r & 7)) << 4)),
                   g_kb + base + (size_t)r * CDIM + g * 8);
    }
    CP_COMMIT();

    float m0 = -1e30f, m1 = -1e30f, l0 = 0.f, l1 = 0.f;
    float O[16][4];
    #pragma unroll
    for (int nt = 0; nt < 16; nt++)
        #pragma unroll
        for (int r = 0; r < 4; r++) O[nt][r] = 0.f;

    const float scale = 0.08838834764831845f;
    int srow = warp * 16 + lq;
    int grow0 = qb * 128 + srow;
    uint32_t frow = (uint32_t)(warp * 16 + lh * 8 + l7);
    int nkb = 2 * (qb + 1);

    for (int kb = 0; kb < nkb; kb++) {
        __syncthreads();

        #pragma unroll
        for (int it = 0; it < 4; it++) {
            int gi = tid + it * 256;
            int r = gi >> 4, g = gi & 15;
            cp_async16(Vb + (uint32_t)(r * 256 + (g >> 3) * 128 + (((g & 7) ^ (r & 7)) << 4)),
                       g_vb + base + (size_t)(kb * 64 + r) * CDIM + g * 8);
        }
        CP_COMMIT();

        bool more = (kb + 1 < nkb);
        if (more) {
            uint32_t ka = ((kb + 1) & 1) ? K1b : K0b;
            #pragma unroll
            for (int it = 0; it < 4; it++) {
                int gi = tid + it * 256;
                int r = gi >> 4, g = gi & 15;
                cp_async16(ka + (uint32_t)(r * 256 + (g >> 3) * 128 + (((g & 7) ^ (r & 7)) << 4)),
                           g_kb + base + (size_t)((kb + 1) * 64 + r) * CDIM + g * 8);
            }
            CP_COMMIT();
        }

        if (more) { CP_WAIT(2); } else { CP_WAIT(1); }
        __syncthreads();

        uint32_t Kc = (kb & 1) ? K1b : K0b;

        float s[8][4];
        #pragma unroll
        for (int nt = 0; nt < 8; nt++)
            #pragma unroll
            for (int r = 0; r < 4; r++) s[nt][r] = 0.f;

        #pragma unroll
        for (int kt = 0; kt < 8; kt++) {
            int ga = kt * 2 + lg;
            uint32_t a0, a1, a2, a3;
            LDMX4(a0, a1, a2, a3,
                  Qb + frow * 256 + (uint32_t)((ga >> 3) * 128 + (((ga & 7) ^ (frow & 7)) << 4)));
            int gb = kt * 2 + lh;
            uint32_t gbo = (uint32_t)((gb >> 3) * 128 + (((gb & 7) ^ l7) << 4));
            #pragma unroll
            for (int np = 0; np < 4; np++) {
                uint32_t krow = (uint32_t)((np * 2 + lg) * 8 + l7);
                uint32_t b0, b1, b2, b3;
                LDMX4(b0, b1, b2, b3, Kc + krow * 256 + gbo);
                MMA_BF16(s[2 * np],     a0, a1, a2, a3, b0, b1);
                MMA_BF16(s[2 * np + 1], a0, a1, a2, a3, b2, b3);
            }
        }

        bool needmask = (kb * 64 + 63 > qb * 128 + warp * 16);
        float t0 = -1e30f, t1 = -1e30f;
        #pragma unroll
        for (int nt = 0; nt < 8; nt++) {
            if (needmask) {
                int cc0 = kb * 64 + nt * 8 + 2 * lr;
                s[nt][0] = (cc0     <= grow0)     ? s[nt][0] * scale : -1e30f;
                s[nt][1] = (cc0 + 1 <= grow0)     ? s[nt][1] * scale : -1e30f;
                s[nt][2] = (cc0     <= grow0 + 8) ? s[nt][2] * scale : -1e30f;
                s[nt][3] = (cc0 + 1 <= grow0 + 8) ? s[nt][3] * scale : -1e30f;
            } else {
                s[nt][0] *= scale; s[nt][1] *= scale;
                s[nt][2] *= scale; s[nt][3] *= scale;
            }
            t0 = fmaxf(t0, fmaxf(s[nt][0], s[nt][1]));
            t1 = fmaxf(t1, fmaxf(s[nt][2], s[nt][3]));
        }
        t0 = fmaxf(t0, __shfl_xor_sync(0xffffffffu, t0, 1));
        t0 = fmaxf(t0, __shfl_xor_sync(0xffffffffu, t0, 2));
        t1 = fmaxf(t1, __shfl_xor_sync(0xffffffffu, t1, 1));
        t1 = fmaxf(t1, __shfl_xor_sync(0xffffffffu, t1, 2));

        float mn0 = fmaxf(m0, t0), mn1 = fmaxf(m1, t1);
        float al0 = __expf(m0 - mn0), al1 = __expf(m1 - mn1);
        float rs0 = 0.f, rs1 = 0.f;
        int pr0 = srow, pr1 = srow + 8;
        #pragma unroll
        for (int nt = 0; nt < 8; nt++) {
            __nv_bfloat162 h0 = __floats2bfloat162_rn(__expf(s[nt][0] - mn0),
                                                      __expf(s[nt][1] - mn0));
            __nv_bfloat162 h1 = __floats2bfloat162_rn(__expf(s[nt][2] - mn1),
                                                      __expf(s[nt][3] - mn1));
            rs0 += __bfloat162float(h0.x) + __bfloat162float(h0.y);
            rs1 += __bfloat162float(h1.x) + __bfloat162float(h1.y);
            *(__nv_bfloat162*)(Pp + pr0 * 128 + ((nt ^ (pr0 & 7)) << 4) + 4 * lr) = h0;
            *(__nv_bfloat162*)(Pp + pr1 * 128 + ((nt ^ (pr1 & 7)) << 4) + 4 * lr) = h1;
        }
        rs0 += __shfl_xor_sync(0xffffffffu, rs0, 1);
        rs0 += __shfl_xor_sync(0xffffffffu, rs0, 2);
        rs1 += __shfl_xor_sync(0xffffffffu, rs1, 1);
        rs1 += __shfl_xor_sync(0xffffffffu, rs1, 2);

        l0 = l0 * al0 + rs0;  l1 = l1 * al1 + rs1;
        m0 = mn0;             m1 = mn1;
        #pragma unroll
        for (int nt = 0; nt < 16; nt++) {
            O[nt][0] *= al0; O[nt][1] *= al0;
            O[nt][2] *= al1; O[nt][3] *= al1;
        }
        __syncwarp();

        if (more) { CP_WAIT(1); } else { CP_WAIT(0); }
        __syncthreads();

        #pragma unroll
        for (int kt = 0; kt < 4; kt++) {
            int ga = kt * 2 + lg;
            uint32_t a0, a1, a2, a3;
            LDMX4(a0, a1, a2, a3,
                  Pb + frow * 128 + (uint32_t)(((ga ^ (frow & 7)) << 4)));
            uint32_t vrow = (uint32_t)(kt * 16 + lh * 8 + l7);
            uint32_t vbase = Vb + vrow * 256;
            uint32_t vsw = (vrow & 7) << 4;
            #pragma unroll
            for (int np = 0; np < 8; np++) {
                int cblk = np * 2 + lg;
                uint32_t b0, b1, b2, b3;
                LDMX4T(b0, b1, b2, b3,
                       vbase + (uint32_t)((cblk >> 3) * 128) +
                       ((((uint32_t)(cblk & 7) << 4) ^ vsw)));
                MMA_BF16(O[2 * np],     a0, a1, a2, a3, b0, b1);
                MMA_BF16(O[2 * np + 1], a0, a1, a2, a3, b2, b3);
            }
        }
    }

    float inv0 = 1.f / l0, inv1 = 1.f / l1;
    size_t row0 = (size_t)b * TSEQ + grow0;
    #pragma unroll
    for (int nt = 0; nt < 16; nt++) {
        int col = h * HDIM + nt * 8 + 2 * lr;
        *(__nv_bfloat162*)(g_att + row0 * CDIM + col) =
            __floats2bfloat162_rn(O[nt][0] * inv0, O[nt][1] * inv0);
        *(__nv_bfloat162*)(g_att + (row0 + 8) * CDIM + col) =
            __floats2bfloat162_rn(O[nt][2] * inv1, O[nt][3] * inv1);
    }
}

// ===================== launch =====================
extern "C" void kernel_launch(void* const* d_in, const int* in_sizes, int n_in,
                              void* d_out, int out_size) {
    const float* x    = (const float*)d_in[0];
    const float* ln_g = (const float*)d_in[1];
    const float* ln_b = (const float*)d_in[2];
    const float* Wq   = (const float*)d_in[3];
    const float* bq   = (const float*)d_in[4];
    const float* Wk   = (const float*)d_in[5];
    const float* bk   = (const float*)d_in[6];
    const float* Wv   = (const float*)d_in[7];
    const float* bv   = (const float*)d_in[8];
    const float* Wo   = (const float*)d_in[9];
    const float* bo   = (const float*)d_in[10];
    float* out = (float*)d_out;

    __nv_bfloat16 *nx, *ap, *wq, *wk, *wv, *wo, *qb, *kb, *vb;
    cudaGetSymbolAddress((void**)&nx, g_nx);
    cudaGetSymbolAddress((void**)&qb, g_qb);
    cudaGetSymbolAddress((void**)&kb, g_kb);
    cudaGetSymbolAddress((void**)&vb, g_vb);
    cudaGetSymbolAddress((void**)&ap, g_att);
    cudaGetSymbolAddress((void**)&wq, g_wq);
    cudaGetSymbolAddress((void**)&wk, g_wk);
    cudaGetSymbolAddress((void**)&wv, g_wv);
    cudaGetSymbolAddress((void**)&wo, g_wo);

    cudaFuncSetAttribute(flash_bf_kernel, cudaFuncAttributeMaxDynamicSharedMemorySize, FLASHB_SMEM);
    cudaFuncSetAttribute(tg5_kernel<0>, cudaFuncAttributeMaxDynamicSharedMemorySize, TG5_SMEM);
    cudaFuncSetAttribute(tg5_kernel<1>, cudaFuncAttributeMaxDynamicSharedMemorySize, TG5_SMEM);

    prep_kernel<<<25600, 256>>>(x, ln_g, ln_b, Wq, Wk, Wv, Wo);

    tg5_kernel<0><<<dim3(16, 64, 3), 256, TG5_SMEM>>>(
        nx, wq, wk, wv, bq, bk, bv, nullptr, nullptr, qb, kb, vb);

    flash_bf_kernel<<<dim3(TSEQ / 128, NHEAD, 4), 256, FLASHB_SMEM>>>();

    tg5_kernel<1><<<dim3(16, 64, 1), 256, TG5_SMEM>>>(
        ap, wo, wo, wo, bo, bo, bo, x, out, nullptr, nullptr, nullptr);
}